// round 12
// baseline (speedup 1.0000x reference)
#include <cuda_runtime.h>
#include <cuda_fp16.h>
#include <math.h>

// ---------------- problem constants ----------------
#define B_  32
#define T_  256
#define D_  512
#define NH_ 8
#define DK_ 64
#define L_  2
#define ML_ 25
#define NWMAT 13

// ---------------- scratch ----------------
__device__ float g_enc[B_*T_*D_];
__device__ float g_tmp[B_*T_*D_];
__device__ float g_q  [B_*T_*D_];
__device__ float g_k  [B_*T_*D_];
__device__ float g_v  [B_*T_*D_];   // V^T halves [512, 8192]
__device__ float g_o  [B_*T_*D_];
__device__ float g_wT [NWMAT*D_*D_];   // halves, perm layout

__device__ __forceinline__ float tanh_fast(float x) {
    float y;
    asm("tanh.approx.f32 %0, %1;" : "=f"(y) : "f"(x));
    return y;
}
__device__ __forceinline__ int pidx32(int k) {
    return ((k & 6) >> 1) * 8 + ((k >> 4) & 1) * 4 + ((k >> 3) & 1) * 2 + (k & 1);
}
__device__ __forceinline__ void st_perm_h2(__half* rowp, int c, float v0, float v1) {
    *reinterpret_cast<__half2*>(&rowp[(c & ~31) + pidx32(c & 31)]) = __floats2half2_rn(v0, v1);
}
__device__ __forceinline__ unsigned pack_h2(float a, float b) {
    __half2 t = __floats2half2_rn(a, b);
    return *reinterpret_cast<unsigned*>(&t);
}

#define CP16(dst, src) \
    asm volatile("cp.async.cg.shared.global [%0], [%1], 16;" :: "r"(dst), "l"(src) : "memory")
#define CPCOMMIT() asm volatile("cp.async.commit_group;" ::: "memory")
#define CPWAIT(n)  asm volatile("cp.async.wait_group %0;" :: "n"(n) : "memory")

__device__ __forceinline__ void mma_f16(float c[4],
                                        unsigned a0, unsigned a1, unsigned a2, unsigned a3,
                                        unsigned b0, unsigned b1)
{
    asm volatile(
        "mma.sync.aligned.m16n8k16.row.col.f32.f16.f16.f32 "
        "{%0,%1,%2,%3}, {%4,%5,%6,%7}, {%8,%9}, {%0,%1,%2,%3};"
        : "+f"(c[0]), "+f"(c[1]), "+f"(c[2]), "+f"(c[3])
        : "r"(a0), "r"(a1), "r"(a2), "r"(a3), "r"(b0), "r"(b1));
}

// ---------------- tiling ----------------
#define ABYT 16384
#define BBYT 8192
#define NSTG3 3
#define TG_SMEM3 (NSTG3 * (ABYT + BBYT))   // 73728

// ===== wide warp tile (64x32) fragment machinery, 4 warps / 128 threads =====
#define FRAG_OFFSETS_W()                                                              \
    unsigned paL[8], pbL[4];                                                          \
    _Pragma("unroll")                                                                 \
    for (int r2 = 0; r2 < 8; r2++) {                                                  \
        int row = wm + r2 * 8 + g;                                                    \
        paL[r2] = (unsigned)(row * 128 + tig * 16 + ((row & 1) << 6));                \
    }                                                                                 \
    _Pragma("unroll")                                                                 \
    for (int r2 = 0; r2 < 4; r2++) {                                                  \
        int rob = wn + r2 * 8 + g;                                                    \
        pbL[r2] = (unsigned)(rob * 128 + tig * 16 + ((rob & 1) << 6));                \
    }

#define MMA_SUB_W(stgA, stgB, XORV) {                                                 \
    uint4 aU[8], bU[4];                                                               \
    _Pragma("unroll")                                                                 \
    for (int r2 = 0; r2 < 8; r2++)                                                    \
        aU[r2] = *reinterpret_cast<const uint4*>((stgA) + (paL[r2] ^ (XORV)));        \
    _Pragma("unroll")                                                                 \
    for (int r2 = 0; r2 < 4; r2++)                                                    \
        bU[r2] = *reinterpret_cast<const uint4*>((stgB) + (pbL[r2] ^ (XORV)));        \
    _Pragma("unroll")                                                                 \
    for (int mt = 0; mt < 4; mt++)                                                    \
        _Pragma("unroll")                                                             \
        for (int nt = 0; nt < 4; nt++) {                                              \
            mma_f16(acc[mt][nt], aU[2*mt].x, aU[2*mt+1].x, aU[2*mt].y, aU[2*mt+1].y,  \
                    bU[nt].x, bU[nt].y);                                              \
            mma_f16(acc[mt][nt], aU[2*mt].z, aU[2*mt+1].z, aU[2*mt].w, aU[2*mt+1].w,  \
                    bU[nt].z, bU[nt].w);                                              \
        }                                                                             \
}

// ===== narrow (32x32) machinery for fused attention (8 warps / 256 threads) =====
#define FRAG_OFFSETS()                                                                \
    unsigned qaL[4], qaH[4], qbL[4], qbH[4];                                          \
    _Pragma("unroll")                                                                 \
    for (int r2 = 0; r2 < 4; r2++) {                                                  \
        int row = wm + r2 * 8 + g;                                                    \
        qaL[r2] = (unsigned)(row * 128 + tig * 16 + ((row & 1) << 6));                \
        qaH[r2] = qaL[r2] ^ 64u;                                                      \
        int rob = wn + r2 * 8 + g;                                                    \
        qbL[r2] = (unsigned)(rob * 128 + tig * 16 + ((rob & 1) << 6));                \
        qbH[r2] = qbL[r2] ^ 64u;                                                      \
    }

#define MMA_SUB2(stgA, stgB, AOFF, BOFF) {                                            \
    uint4 aU[4], bU[4];                                                               \
    _Pragma("unroll")                                                                 \
    for (int r2 = 0; r2 < 4; r2++) {                                                  \
        aU[r2] = *reinterpret_cast<const uint4*>((stgA) + (AOFF)[r2]);                \
        bU[r2] = *reinterpret_cast<const uint4*>((stgB) + (BOFF)[r2]);                \
    }                                                                                 \
    _Pragma("unroll")                                                                 \
    for (int mt = 0; mt < 2; mt++)                                                    \
        _Pragma("unroll")                                                             \
        for (int nt = 0; nt < 4; nt++) {                                              \
            mma_f16(acc[mt][nt], aU[2*mt].x, aU[2*mt+1].x, aU[2*mt].y, aU[2*mt+1].y,  \
                    bU[nt].x, bU[nt].y);                                              \
            mma_f16(acc[mt][nt], aU[2*mt].z, aU[2*mt+1].z, aU[2*mt].w, aU[2*mt+1].w,  \
                    bU[nt].z, bU[nt].w);                                              \
        }                                                                             \
}

// ---------------- prep ----------------
__global__ void prep_kernel(const float* __restrict__ x, const float* __restrict__ pos,
                            const int* __restrict__ ewp, float* __restrict__ enc)
{
    __shared__ float tile[32][33];
    int b  = blockIdx.z;
    int d0 = blockIdx.x * 32, t0 = blockIdx.y * 32;
    int tx = threadIdx.x, ty = threadIdx.y;
    const float* xb = x + (long long)b * D_ * T_;
    #pragma unroll
    for (int i = 0; i < 4; i++) {
        int d = ty + i * 8;
        tile[d][tx] = xb[(long long)(d0 + d) * T_ + t0 + tx];
    }
    __syncthreads();
    #pragma unroll
    for (int i = 0; i < 4; i++) {
        int tl = ty + i * 8;
        int t = t0 + tl, d = d0 + tx;
        int pr = ewp[t];
        enc[(((long long)b * T_) + t) * D_ + d] =
            tile[tx][tl] * 22.62741699796952f + pos[(long long)pr * D_ + d];
    }
}

// ---------------- weight transpose -> half perm ----------------
struct WP { const float* w[NWMAT]; };
__global__ void wtrans_kernel(WP p, __half* __restrict__ out)
{
    __shared__ float t[32][33];
    int mi = blockIdx.z;
    const float* W = p.w[mi];
    __half* O = out + (long long)mi * D_ * D_;
    int n0 = blockIdx.x * 32, k0 = blockIdx.y * 32;
    int tx = threadIdx.x, ty = threadIdx.y;
    #pragma unroll
    for (int i = 0; i < 4; i++) {
        int k = k0 + ty + i * 8;
        t[ty + i * 8][tx] = W[(long long)k * D_ + n0 + tx];
    }
    __syncthreads();
    #pragma unroll
    for (int i = 0; i < 4; i++) {
        int n = n0 + ty + i * 8;
        O[(long long)n * D_ + k0 + pidx32(tx)] = __float2half(t[tx][ty + i * 8]);
    }
}

// ---------------- layernorm -> half perm ----------------
__global__ void ln_kernel(const float* __restrict__ in, __half* __restrict__ out,
                          const float* __restrict__ gs, const float* __restrict__ gb)
{
    int row  = blockIdx.x * 8 + threadIdx.y;
    int lane = threadIdx.x;
    const float* r = in + (long long)row * D_;
    float4 xv[4];
    #pragma unroll
    for (int j = 0; j < 4; j++)
        xv[j] = *reinterpret_cast<const float4*>(&r[(j * 32 + lane) * 4]);
    float s = 0.f;
    #pragma unroll
    for (int j = 0; j < 4; j++) s += xv[j].x + xv[j].y + xv[j].z + xv[j].w;
    #pragma unroll
    for (int o = 16; o; o >>= 1) s += __shfl_xor_sync(0xffffffffu, s, o);
    float mean = s * (1.0f / D_);
    float vs = 0.f;
    #pragma unroll
    for (int j = 0; j < 4; j++) {
        float a = xv[j].x - mean, b2 = xv[j].y - mean, c = xv[j].z - mean, d = xv[j].w - mean;
        vs += a * a + b2 * b2 + c * c + d * d;
    }
    #pragma unroll
    for (int o = 16; o; o >>= 1) vs += __shfl_xor_sync(0xffffffffu, vs, o);
    float rstd = rsqrtf(vs * (1.0f / D_) + 1e-5f);
    __half* w = out + (long long)row * D_;
    #pragma unroll
    for (int j = 0; j < 4; j++) {
        int c0 = (j * 32 + lane) * 4;
        float4 sv = *reinterpret_cast<const float4*>(&gs[c0]);
        float4 bv = *reinterpret_cast<const float4*>(&gb[c0]);
        float tx = (xv[j].x - mean) * rstd * sv.x + bv.x;
        float ty = (xv[j].y - mean) * rstd * sv.y + bv.y;
        float tz = (xv[j].z - mean) * rstd * sv.z + bv.z;
        float tw = (xv[j].w - mean) * rstd * sv.w + bv.w;
        st_perm_h2(w, c0,     tx, ty);
        st_perm_h2(w, c0 + 2, tz, tw);
    }
}

// ======================================================================
// fp16 MMA GEMM: 128-thread CTA, 4 warps of 64x32. 3-stage cp.async.
// ======================================================================
struct TGB { const __half* A; const __half* Bt; void* C; const float* bias;
             const float* resid; int flags; int ldc; int bxShift; };
struct TGArgs { TGB t[3]; };

__global__ void __launch_bounds__(128, 3) tgemm_kernel(TGArgs args)
{
    extern __shared__ char smc[];
    char* sA = smc;
    char* sB = smc + NSTG3 * ABYT;
    TGB tb = args.t[blockIdx.z];

    int tid = threadIdx.x, w = tid >> 5, lane = tid & 31;
    int g = lane >> 2, tig = lane & 3;
    int bx = blockIdx.x;
    int bn = (bx & ((1 << tb.bxShift) - 1)) * 64;
    int bm = (bx >> tb.bxShift) * 128;
    int wm = (w & 1) * 64, wn = (w >> 1) * 32;

    unsigned uA = (unsigned)__cvta_generic_to_shared(sA);
    unsigned uB = (unsigned)__cvta_generic_to_shared(sB);
    int crow = tid >> 3, cch = tid & 7;
    unsigned cxor = (unsigned)((cch * 16) ^ ((crow & 1) << 6));
    unsigned aBase = uA + (unsigned)(crow * 128) + cxor;
    unsigned bBase = uB + (unsigned)(crow * 128) + cxor;
    const __half* aSrc = tb.A  + (long long)(bm + crow) * D_ + cch * 8;
    const __half* bSrc = tb.Bt + (long long)(bn + crow) * D_ + cch * 8;

    FRAG_OFFSETS_W()

    float acc[4][4][4];
    #pragma unroll
    for (int i = 0; i < 4; i++)
        #pragma unroll
        for (int j = 0; j < 4; j++)
            #pragma unroll
            for (int q = 0; q < 4; q++) acc[i][j][q] = 0.f;

    #pragma unroll
    for (int s = 0; s < 2; s++) {
        #pragma unroll
        for (int i = 0; i < 8; i++)
            CP16(aBase + (unsigned)(s * ABYT + i * 2048), aSrc + i * 16 * D_ + s * 64);
        #pragma unroll
        for (int i = 0; i < 4; i++)
            CP16(bBase + (unsigned)(s * BBYT + i * 2048), bSrc + i * 16 * D_ + s * 64);
        CPCOMMIT();
    }

    const int NKT = D_ / 64;   // 8
    #pragma unroll
    for (int kt = 0; kt < NKT; kt++) {
        CPWAIT(1);
        __syncthreads();
        int s = kt % NSTG3;
        char* pA = sA + s * ABYT;
        char* pB = sB + s * BBYT;
        if (kt + 2 < NKT) {
            int rs = (kt + 2) % NSTG3;
            int ko = (kt + 2) * 64;
            #pragma unroll
            for (int i = 0; i < 8; i++)
                CP16(aBase + (unsigned)(rs * ABYT + i * 2048), aSrc + i * 16 * D_ + ko);
            #pragma unroll
            for (int i = 0; i < 4; i++)
                CP16(bBase + (unsigned)(rs * BBYT + i * 2048), bSrc + i * 16 * D_ + ko);
        }
        CPCOMMIT();
        MMA_SUB_W(pA, pB, 0u)
        MMA_SUB_W(pA, pB, 64u)
    }

    int flags = tb.flags, ldc = tb.ldc;
    #pragma unroll
    for (int mt = 0; mt < 4; mt++) {
        #pragma unroll
        for (int nt = 0; nt < 4; nt++) {
            int row0 = bm + wm + mt * 16 + g;
            int col  = bn + wn + nt * 8 + 2 * tig;
            float v00 = acc[mt][nt][0], v01 = acc[mt][nt][1];
            float v10 = acc[mt][nt][2], v11 = acc[mt][nt][3];
            if (flags & 4) {
                float b0 = tb.bias[row0], b1 = tb.bias[row0 + 8];
                v00 += b0; v01 += b0; v10 += b1; v11 += b1;
            } else {
                float2 bv = *reinterpret_cast<const float2*>(&tb.bias[col]);
                v00 += bv.x; v01 += bv.y; v10 += bv.x; v11 += bv.y;
            }
            if (flags & 1) {
                v00 = fmaxf(v00, 0.f); v01 = fmaxf(v01, 0.f);
                v10 = fmaxf(v10, 0.f); v11 = fmaxf(v11, 0.f);
            }
            if (tb.resid) {
                float2 r0 = *reinterpret_cast<const float2*>(
                    &tb.resid[(long long)row0 * ldc + col]);
                float2 r1 = *reinterpret_cast<const float2*>(
                    &tb.resid[(long long)(row0 + 8) * ldc + col]);
                v00 += r0.x; v01 += r0.y; v10 += r1.x; v11 += r1.y;
            }
            if (flags & 2) {
                __half* r0p = (__half*)tb.C + (long long)row0 * ldc;
                __half* r1p = (__half*)tb.C + (long long)(row0 + 8) * ldc;
                st_perm_h2(r0p, col, v00, v01);
                st_perm_h2(r1p, col, v10, v11);
            } else {
                float* Cf = (float*)tb.C;
                *reinterpret_cast<float2*>(&Cf[(long long)row0 * ldc + col]) =
                    make_float2(v00, v01);
                *reinterpret_cast<float2*>(&Cf[(long long)(row0 + 8) * ldc + col]) =
                    make_float2(v10, v11);
            }
        }
    }
}

// ======================================================================
// FUSED attention: QK^T + softmax + PV in one kernel.
// CTA = 32 q-rows x all 256 keys, 256 threads (8 warps, one 32-key slice each).
// smem: [sV 32KB swizzled 64x512][sQ 4KB][region 64KB: sK(32KB)/red(8x8KB)]
// ======================================================================
#define FA_SV   0
#define FA_SQ   32768
#define FA_RG   36864
#define FA_SMEM (36864 + 65536)   // 102400

__global__ void __launch_bounds__(256, 1) fa_kernel(
    const __half* __restrict__ q, const __half* __restrict__ k,
    const __half* __restrict__ vT, __half* __restrict__ O)
{
    extern __shared__ char smc[];
    char* sV = smc + FA_SV;
    char* sQ = smc + FA_SQ;
    char* sK = smc + FA_RG;
    __shared__ float sred[32][8];

    int z = blockIdx.z, b = z >> 3, h = z & 7;
    int bm = blockIdx.x * 32;
    int tid = threadIdx.x, w = tid >> 5, lane = tid & 31;
    int g = lane >> 2, tig = lane & 3;
    int wm = 0, wn = w * 32;

    unsigned uQ = (unsigned)__cvta_generic_to_shared(sQ);
    unsigned uK = (unsigned)__cvta_generic_to_shared(sK);
    unsigned uV = (unsigned)__cvta_generic_to_shared(sV);

    {   // loads: Q 1/thread, K 8/thread, V 8/thread
        int row = tid >> 3, ch = tid & 7;
        unsigned cx = (unsigned)((ch * 16) ^ ((row & 1) << 6));
        CP16(uQ + (unsigned)(row * 128) + cx,
             q + (long long)(b * T_ + bm + row) * D_ + h * DK_ + ch * 8);
        #pragma unroll
        for (int i = 0; i < 8; i++) {
            int idx = tid + i * 256;
            int br = idx >> 3, bch = idx & 7;
            unsigned bx2 = (unsigned)((bch * 16) ^ ((br & 1) << 6));
            CP16(uK + (unsigned)(br * 128) + bx2,
                 k + (long long)(b * T_ + br) * D_ + h * DK_ + bch * 8);
        }
        #pragma unroll
        for (int i = 0; i < 8; i++) {
            int idx = tid + i * 256;
            int vr = idx >> 5, vc = idx & 31;          // vr 0..63, vc 0..31
            unsigned vx = (unsigned)((vc * 16) ^ ((vr & 7) << 4));
            CP16(uV + (unsigned)(vr * 512) + vx,
                 vT + (long long)(h * DK_ + vr) * (B_ * T_) + b * T_ + vc * 8);
        }
    }
    CPCOMMIT();

    FRAG_OFFSETS()

    float acc[2][4][4];
    #pragma unroll
    for (int i = 0; i < 2; i++)
        #pragma unroll
        for (int j = 0; j < 4; j++)
            #pragma unroll
            for (int qq = 0; qq < 4; qq++) acc[i][j][qq] = 0.f;

    CPWAIT(0);
    __syncthreads();
    MMA_SUB2(sQ, sK, qaL, qbL)
    MMA_SUB2(sQ, sK, qaH, qbH)

    #pragma unroll
    for (int i = 0; i < 2; i++)
        #pragma unroll
        for (int j = 0; j < 4; j++)
            #pragma unroll
            for (int qq = 0; qq < 4; qq++) acc[i][j][qq] *= 0.125f;

    // ---- softmax over the full 256-key rows ----
    float rmx[4];
    #pragma unroll
    for (int rs = 0; rs < 4; rs++) {
        int mt = rs >> 1, hh = (rs & 1) * 2;
        float m = -3.0e38f;
        #pragma unroll
        for (int nt = 0; nt < 4; nt++)
            m = fmaxf(m, fmaxf(acc[mt][nt][hh], acc[mt][nt][hh + 1]));
        m = fmaxf(m, __shfl_xor_sync(0xffffffffu, m, 1));
        m = fmaxf(m, __shfl_xor_sync(0xffffffffu, m, 2));
        rmx[rs] = m;
        if (tig == 0) sred[mt * 16 + (rs & 1) * 8 + g][w] = m;
    }
    __syncthreads();
    #pragma unroll
    for (int rs = 0; rs < 4; rs++) {
        int rr = (rs >> 1) * 16 + (rs & 1) * 8 + g;
        float m = sred[rr][0];
        #pragma unroll
        for (int ww = 1; ww < 8; ww++) m = fmaxf(m, sred[rr][ww]);
        rmx[rs] = m;
    }
    __syncthreads();
    float rsum[4];
    #pragma unroll
    for (int rs = 0; rs < 4; rs++) {
        int mt = rs >> 1, hh = (rs & 1) * 2;
        float s = 0.f;
        #pragma unroll
        for (int nt = 0; nt < 4; nt++) {
            float e0 = __expf(acc[mt][nt][hh]     - rmx[rs]);
            float e1 = __expf(acc[mt][nt][hh + 1] - rmx[rs]);
            acc[mt][nt][hh]     = e0;
            acc[mt][nt][hh + 1] = e1;
            s += e0 + e1;
        }
        s += __shfl_xor_sync(0xffffffffu, s, 1);
        s += __shfl_xor_sync(0xffffffffu, s, 2);
        rsum[rs] = s;
        if (tig == 0) sred[mt * 16 + (rs & 1) * 8 + g][w] = s;
    }
    __syncthreads();
    #pragma unroll
    for (int rs = 0; rs < 4; rs++) {
        int rr = (rs >> 1) * 16 + (rs & 1) * 8 + g;
        float s = sred[rr][0];
        #pragma unroll
        for (int ww = 1; ww < 8; ww++) s += sred[rr][ww];
        rsum[rs] = 1.0f / s;
    }

    // ---- repack P fragments (C-frag of S == A-frag of PV) ----
    unsigned aF[2][2][4];
    #pragma unroll
    for (int mt = 0; mt < 2; mt++) {
        float i0 = rsum[mt * 2], i1 = rsum[mt * 2 + 1];
        #pragma unroll
        for (int j = 0; j < 2; j++) {
            aF[mt][j][0] = pack_h2(acc[mt][2*j][0] * i0, acc[mt][2*j][1] * i0);
            aF[mt][j][1] = pack_h2(acc[mt][2*j][2] * i1, acc[mt][2*j][3] * i1);
            aF[mt][j][2] = pack_h2(acc[mt][2*j+1][0] * i0, acc[mt][2*j+1][1] * i0);
            aF[mt][j][3] = pack_h2(acc[mt][2*j+1][2] * i1, acc[mt][2*j+1][3] * i1);
        }
    }

    // ---- PV: each warp computes partial O (32 x 64) over its 32 keys ----
    float accO[2][8][4];
    #pragma unroll
    for (int i = 0; i < 2; i++)
        #pragma unroll
        for (int j = 0; j < 8; j++)
            #pragma unroll
            for (int qq = 0; qq < 4; qq++) accO[i][j][qq] = 0.f;

    {
        uint4 bU[8];
        #pragma unroll
        for (int nb = 0; nb < 8; nb++) {
            int row = nb * 8 + g;
            bU[nb] = *reinterpret_cast<const uint4*>(
                sV + row * 512 + ((w * 64 + tig * 16) ^ ((row & 7) << 4)));
        }
        #pragma unroll
        for (int mt = 0; mt < 2; mt++)
            #pragma unroll
            for (int nb = 0; nb < 8; nb++) {
                mma_f16(accO[mt][nb], aF[mt][0][0], aF[mt][0][1], aF[mt][0][2], aF[mt][0][3],
                        bU[nb].x, bU[nb].y);
                mma_f16(accO[mt][nb], aF[mt][1][0], aF[mt][1][1], aF[mt][1][2], aF[mt][1][3],
                        bU[nb].z, bU[nb].w);
            }
    }

    // ---- cross-warp reduction: region becomes 8 buffers of 32x64 fp32 ----
    __syncthreads();   // all warps done reading sK (region); safe to overwrite
    float* myred = reinterpret_cast<float*>(smc + FA_RG) + w * 2048;
    #pragma unroll
    for (int mt = 0; mt < 2; mt++)
        #pragma unroll
        for (int nb = 0; nb < 8; nb++) {
            int r0 = mt * 16 + g;
            *reinterpret_cast<float2*>(&myred[r0 * 64 + nb * 8 + 2 * tig]) =
                make_float2(accO[mt][nb][0], accO[mt][nb][1]);
            *reinterpret_cast<float2*>(&myred[(r0 + 8) * 64 + nb * 8 + 2 * tig]) =
                make_float2(accO[mt][nb][2], accO[mt][nb][3]);
        }
    __syncthreads();

    {   // final sum of 8 partials; each thread owns 8 consecutive elements
        const float* red = reinterpret_cast<const float*>(smc + FA_RG);
        int e0 = tid * 8;
        int r = e0 >> 6, c = e0 & 63;
        float v[8];
        #pragma unroll
        for (int j = 0; j < 8; j++) v[j] = 0.f;
        #pragma unroll
        for (int ww = 0; ww < 8; ww++) {
            const float* bw = red + ww * 2048 + e0;
            float4 x0 = *reinterpret_cast<const float4*>(bw);
            float4 x1 = *reinterpret_cast<const float4*>(bw + 4);
            v[0] += x0.x; v[1] += x0.y; v[2] += x0.z; v[3] += x0.w;
            v[4] += x1.x; v[5] += x1.y; v[6] += x1.z; v[7] += x1.w;
        }
        __half* orow = O + (long long)(b * T_ + bm + r) * D_;
        int colg = h * DK_ + c;
        st_perm_h2(orow, colg,     v[0], v[1]);
        st_perm_h2(orow, colg + 2, v[2], v[3]);
        st_perm_h2(orow, colg + 4, v[4], v[5]);
        st_perm_h2(orow, colg + 6, v[6], v[7]);
    }
}

// ---------------- PVAM head: 5 query positions per block ----------------
__global__ void __launch_bounds__(256) pvam_kernel(
    const float* __restrict__ wf, const float* __restrict__ emb,
    const int* __restrict__ gwp, const float* __restrict__ fc1,
    float* __restrict__ out)
{
    __shared__ float s_wp[5][D_];
    __shared__ float s_f[D_];
    __shared__ float s_sc[5][T_];
    __shared__ float s_red[40];
    int mg = blockIdx.x * 5, b = blockIdx.y;
    int tid = threadIdx.x;
    for (int i = tid; i < 5 * D_; i += 256) {
        int j = i >> 9, c = i & (D_ - 1);
        s_wp[j][c] = emb[(long long)gwp[mg + j] * D_ + c];
    }
    for (int i = tid; i < D_; i += 256) s_f[i] = fc1[i];
    __syncthreads();

    const float* wr = wf + ((long long)b * T_ + tid) * D_;
    float sc[5] = {0.f, 0.f, 0.f, 0.f, 0.f};
    for (int c4 = 0; c4 < D_ / 4; c4++) {
        float4 wv = *reinterpret_cast<const float4*>(&wr[c4 * 4]);
        float4 fv = *reinterpret_cast<const float4*>(&s_f[c4 * 4]);
        #pragma unroll
        for (int j = 0; j < 5; j++) {
            float4 pv = *reinterpret_cast<const float4*>(&s_wp[j][c4 * 4]);
            sc[j] += tanh_fast(wv.x + pv.x) * fv.x;
            sc[j] += tanh_fast(wv.y + pv.y) * fv.y;
            sc[j] += tanh_fast(wv.z + pv.z) * fv.z;
            sc[j] += tanh_fast(wv.w + pv.w) * fv.w;
        }
    }

    int wid = tid >> 5, lane = tid & 31;
    #pragma unroll
    for (int j = 0; j < 5; j++) {
        float mv = sc[j];
        #pragma unroll
        for (int o = 16; o; o >>= 1) mv = fmaxf(mv, __shfl_xor_sync(0xffffffffu, mv, o));
        if (lane == 0) s_red[wid] = mv;
        __syncthreads();
        if (tid < 32) {
            float t = (tid < 8) ? s_red[tid] : -3.0e38f;
            #pragma unroll
            for (int o = 4; o; o >>= 1) t = fmaxf(t, __shfl_xor_sync(0xffffffffu, t, o));
            if (tid == 0) s_red[32] = t;
        }
        __syncthreads();
        float e = __expf(sc[j] - s_red[32]);
        float sv = e;
        #pragma unroll
        for (int o = 16; o; o >>= 1) sv += __shfl_xor_sync(0xffffffffu, sv, o);
        if (lane == 0) s_red[8 + wid] = sv;
        __syncthreads();
        if (tid < 32) {
            float t = (tid < 8) ? s_red[8 + tid] : 0.f;
            #pragma unroll
            for (int o = 4; o; o >>= 1) t += __shfl_xor_sync(0xffffffffu, t, o);
            if (tid == 0) s_red[33] = t;
        }
        __syncthreads();
        s_sc[j][tid] = e * (1.0f / s_red[33]);
        __syncthreads();
    }

    const float* base = wf + (long long)b * T_ * D_;
    int c0 = tid, c1 = tid + 256;
    float a0[5] = {0.f, 0.f, 0.f, 0.f, 0.f};
    float a1[5] = {0.f, 0.f, 0.f, 0.f, 0.f};
    #pragma unroll 4
    for (int t = 0; t < T_; t++) {
        float w0 = base[(long long)t * D_ + c0];
        float w1 = base[(long long)t * D_ + c1];
        #pragma unroll
        for (int j = 0; j < 5; j++) {
            float s = s_sc[j][t];
            a0[j] += s * w0;
            a1[j] += s * w1;
        }
    }
    #pragma unroll
    for (int j = 0; j < 5; j++) {
        long long ob = ((long long)b * ML_ + mg + j) * D_;
        out[ob + c0] = a0[j];
        out[ob + c1] = a1[j];
    }
}

// ---------------- host launcher ----------------
extern "C" void kernel_launch(void* const* d_in, const int* in_sizes, int n_in,
                              void* d_out, int out_size)
{
    const float* x    = (const float*)d_in[0];
    const int*   ewp  = (const int*)  d_in[1];
    const int*   gwp  = (const int*)  d_in[2];
    const float* pos  = (const float*)d_in[3];
    const float* ln1s = (const float*)d_in[4];
    const float* ln1b = (const float*)d_in[5];
    const float* Wq   = (const float*)d_in[6];
    const float* bq   = (const float*)d_in[7];
    const float* Wk   = (const float*)d_in[8];
    const float* bk   = (const float*)d_in[9];
    const float* Wv   = (const float*)d_in[10];
    const float* bv   = (const float*)d_in[11];
    const float* Wo   = (const float*)d_in[12];
    const float* bo   = (const float*)d_in[13];
    const float* ln2s = (const float*)d_in[14];
    const float* ln2b = (const float*)d_in[15];
    const float* W1   = (const float*)d_in[16];
    const float* b1   = (const float*)d_in[17];
    const float* W2   = (const float*)d_in[18];
    const float* b2   = (const float*)d_in[19];
    const float* lnfs = (const float*)d_in[20];
    const float* lnfb = (const float*)d_in[21];
    const float* fc0w = (const float*)d_in[22];
    const float* fc0b = (const float*)d_in[23];
    const float* emb  = (const float*)d_in[24];
    const float* fc1  = (const float*)d_in[25];

    static float *enc = nullptr, *tmp, *q, *k, *v, *o, *wT;
    if (!enc) {
        cudaGetSymbolAddress((void**)&enc, g_enc);
        cudaGetSymbolAddress((void**)&tmp, g_tmp);
        cudaGetSymbolAddress((void**)&q,   g_q);
        cudaGetSymbolAddress((void**)&k,   g_k);
        cudaGetSymbolAddress((void**)&v,   g_v);
        cudaGetSymbolAddress((void**)&o,   g_o);
        cudaGetSymbolAddress((void**)&wT,  g_wT);
        cudaFuncSetAttribute(tgemm_kernel,
                             cudaFuncAttributeMaxDynamicSharedMemorySize, TG_SMEM3);
        cudaFuncSetAttribute(fa_kernel,
                             cudaFuncAttributeMaxDynamicSharedMemorySize, FA_SMEM);
    }

    __half* tmp_h = (__half*)tmp;
    __half* q_h   = (__half*)q;
    __half* k_h   = (__half*)k;
    __half* v_h   = (__half*)v;
    __half* o_h   = (__half*)o;
    __half* wT_h  = (__half*)wT;

    const long long DD = (long long)D_ * D_;

    WP wp;
    wp.w[0]  = Wq;       wp.w[1]  = Wk;       wp.w[2]  = Wv;
    wp.w[3]  = Wo;       wp.w[4]  = W1;       wp.w[5]  = W2;
    wp.w[6]  = Wq + DD;  wp.w[7]  = Wk + DD;  wp.w[8]  = Wv + DD;
    wp.w[9]  = Wo + DD;  wp.w[10] = W1 + DD;  wp.w[11] = W2 + DD;
    wp.w[12] = fc0w;
    wtrans_kernel<<<dim3(16, 16, NWMAT), dim3(32, 8)>>>(wp, wT_h);

    prep_kernel<<<dim3(D_ / 32, T_ / 32, B_), dim3(32, 8)>>>(x, pos, ewp, enc);

    const int MT = B_ * T_;   // 8192

    for (int l = 0; l < L_; l++) {
        int vo = l * D_;
        const __half* wq = wT_h + (l * 6 + 0) * DD;
        const __half* wk = wT_h + (l * 6 + 1) * DD;
        const __half* wv = wT_h + (l * 6 + 2) * DD;
        const __half* wo = wT_h + (l * 6 + 3) * DD;
        const __half* w1 = wT_h + (l * 6 + 4) * DD;
        const __half* w2 = wT_h + (l * 6 + 5) * DD;

        ln_kernel<<<MT / 8, dim3(32, 8)>>>(enc, tmp_h, ln1s + vo, ln1b + vo);

        TGArgs aqkv;
        aqkv.t[0] = {tmp_h, wq, q_h, bq + vo, nullptr, 2, D_, 3};
        aqkv.t[1] = {tmp_h, wk, k_h, bk + vo, nullptr, 2, D_, 3};
        aqkv.t[2] = {wv, tmp_h, v_h, bv + vo, nullptr, 2 | 4, MT, 7};
        tgemm_kernel<<<dim3(512, 1, 3), 128, TG_SMEM3>>>(aqkv);

        fa_kernel<<<dim3(T_ / 32, 1, B_ * NH_), 256, FA_SMEM>>>(q_h, k_h, v_h, o_h);

        TGArgs ao; ao.t[0] = {o_h, wo, enc, bo + vo, enc, 0, D_, 3};
        tgemm_kernel<<<dim3(512, 1, 1), 128, TG_SMEM3>>>(ao);

        ln_kernel<<<MT / 8, dim3(32, 8)>>>(enc, tmp_h, ln2s + vo, ln2b + vo);
        TGArgs a1; a1.t[0] = {tmp_h, w1, o_h, b1 + vo, nullptr, 3, D_, 3};
        tgemm_kernel<<<dim3(512, 1, 1), 128, TG_SMEM3>>>(a1);
        TGArgs a2; a2.t[0] = {o_h, w2, enc, b2 + vo, enc, 0, D_, 3};
        tgemm_kernel<<<dim3(512, 1, 1), 128, TG_SMEM3>>>(a2);
    }

    ln_kernel<<<MT / 8, dim3(32, 8)>>>(enc, tmp_h, lnfs, lnfb);
    TGArgs af; af.t[0] = {tmp_h, wT_h + 12 * DD, q, fc0b, nullptr, 0, D_, 3};
    tgemm_kernel<<<dim3(512, 1, 1), 128, TG_SMEM3>>>(af);

    pvam_kernel<<<dim3(ML_ / 5, B_), 256>>>(q, emb, gwp, fc1, (float*)d_out);
}

// round 13
// speedup vs baseline: 1.0122x; 1.0122x over previous
#include <cuda_runtime.h>
#include <cuda_fp16.h>
#include <math.h>

// ---------------- problem constants ----------------
#define B_  32
#define T_  256
#define D_  512
#define NH_ 8
#define DK_ 64
#define L_  2
#define ML_ 25
#define NWMAT 13

// ---------------- scratch ----------------
__device__ float g_enc[B_*T_*D_];
__device__ float g_tmp[B_*T_*D_];
__device__ float g_q  [B_*T_*D_];
__device__ float g_k  [B_*T_*D_];
__device__ float g_v  [B_*T_*D_];   // V^T halves [512, 8192]
__device__ float g_o  [B_*T_*D_];
__device__ float g_p  [B_*NH_*T_*T_];  // P halves, pitch 256
__device__ float g_wT [NWMAT*D_*D_];   // halves, perm layout

__device__ __forceinline__ float tanh_fast(float x) {
    float y;
    asm("tanh.approx.f32 %0, %1;" : "=f"(y) : "f"(x));
    return y;
}
__device__ __forceinline__ int pidx32(int k) {
    return ((k & 6) >> 1) * 8 + ((k >> 4) & 1) * 4 + ((k >> 3) & 1) * 2 + (k & 1);
}
__device__ __forceinline__ void st_perm_h2(__half* rowp, int c, float v0, float v1) {
    *reinterpret_cast<__half2*>(&rowp[(c & ~31) + pidx32(c & 31)]) = __floats2half2_rn(v0, v1);
}

#define CP16(dst, src) \
    asm volatile("cp.async.cg.shared.global [%0], [%1], 16;" :: "r"(dst), "l"(src) : "memory")
#define CPCOMMIT() asm volatile("cp.async.commit_group;" ::: "memory")
#define CPWAIT(n)  asm volatile("cp.async.wait_group %0;" :: "n"(n) : "memory")

__device__ __forceinline__ void mma_f16(float c[4],
                                        unsigned a0, unsigned a1, unsigned a2, unsigned a3,
                                        unsigned b0, unsigned b1)
{
    asm volatile(
        "mma.sync.aligned.m16n8k16.row.col.f32.f16.f16.f32 "
        "{%0,%1,%2,%3}, {%4,%5,%6,%7}, {%8,%9}, {%0,%1,%2,%3};"
        : "+f"(c[0]), "+f"(c[1]), "+f"(c[2]), "+f"(c[3])
        : "r"(a0), "r"(a1), "r"(a2), "r"(a3), "r"(b0), "r"(b1));
}

// ---------------- tiling ----------------
#define ABYT 16384
#define BBYT 8192
#define NSTG3 3
#define TG_SMEM3 (NSTG3 * (ABYT + BBYT))   // 73728

// ===== wide warp tile (64x32) fragment machinery =====
#define FRAG_OFFSETS_W()                                                              \
    unsigned paL[8], pbL[4];                                                          \
    _Pragma("unroll")                                                                 \
    for (int r2 = 0; r2 < 8; r2++) {                                                  \
        int row = wm + r2 * 8 + g;                                                    \
        paL[r2] = (unsigned)(row * 128 + tig * 16 + ((row & 1) << 6));                \
    }                                                                                 \
    _Pragma("unroll")                                                                 \
    for (int r2 = 0; r2 < 4; r2++) {                                                  \
        int rob = wn + r2 * 8 + g;                                                    \
        pbL[r2] = (unsigned)(rob * 128 + tig * 16 + ((rob & 1) << 6));                \
    }

#define MMA_SUB_W(stgA, stgB, XORV) {                                                 \
    uint4 aU[8], bU[4];                                                               \
    _Pragma("unroll")                                                                 \
    for (int r2 = 0; r2 < 8; r2++)                                                    \
        aU[r2] = *reinterpret_cast<const uint4*>((stgA) + (paL[r2] ^ (XORV)));        \
    _Pragma("unroll")                                                                 \
    for (int r2 = 0; r2 < 4; r2++)                                                    \
        bU[r2] = *reinterpret_cast<const uint4*>((stgB) + (pbL[r2] ^ (XORV)));        \
    _Pragma("unroll")                                                                 \
    for (int mt = 0; mt < 4; mt++)                                                    \
        _Pragma("unroll")                                                             \
        for (int nt = 0; nt < 4; nt++) {                                              \
            mma_f16(acc[mt][nt], aU[2*mt].x, aU[2*mt+1].x, aU[2*mt].y, aU[2*mt+1].y,  \
                    bU[nt].x, bU[nt].y);                                              \
            mma_f16(acc[mt][nt], aU[2*mt].z, aU[2*mt+1].z, aU[2*mt].w, aU[2*mt+1].w,  \
                    bU[nt].z, bU[nt].w);                                              \
        }                                                                             \
}

// ---------------- prep ----------------
__global__ void prep_kernel(const float* __restrict__ x, const float* __restrict__ pos,
                            const int* __restrict__ ewp, float* __restrict__ enc)
{
    __shared__ float tile[32][33];
    int b  = blockIdx.z;
    int d0 = blockIdx.x * 32, t0 = blockIdx.y * 32;
    int tx = threadIdx.x, ty = threadIdx.y;
    const float* xb = x + (long long)b * D_ * T_;
    #pragma unroll
    for (int i = 0; i < 4; i++) {
        int d = ty + i * 8;
        tile[d][tx] = xb[(long long)(d0 + d) * T_ + t0 + tx];
    }
    __syncthreads();
    #pragma unroll
    for (int i = 0; i < 4; i++) {
        int tl = ty + i * 8;
        int t = t0 + tl, d = d0 + tx;
        int pr = ewp[t];
        enc[(((long long)b * T_) + t) * D_ + d] =
            tile[tx][tl] * 22.62741699796952f + pos[(long long)pr * D_ + d];
    }
}

// ---------------- weight transpose -> half perm ----------------
struct WP { const float* w[NWMAT]; };
__global__ void wtrans_kernel(WP p, __half* __restrict__ out)
{
    __shared__ float t[32][33];
    int mi = blockIdx.z;
    const float* W = p.w[mi];
    __half* O = out + (long long)mi * D_ * D_;
    int n0 = blockIdx.x * 32, k0 = blockIdx.y * 32;
    int tx = threadIdx.x, ty = threadIdx.y;
    #pragma unroll
    for (int i = 0; i < 4; i++) {
        int k = k0 + ty + i * 8;
        t[ty + i * 8][tx] = W[(long long)k * D_ + n0 + tx];
    }
    __syncthreads();
    #pragma unroll
    for (int i = 0; i < 4; i++) {
        int n = n0 + ty + i * 8;
        O[(long long)n * D_ + k0 + pidx32(tx)] = __float2half(t[tx][ty + i * 8]);
    }
}

// ---------------- layernorm -> half perm ----------------
__global__ void ln_kernel(const float* __restrict__ in, __half* __restrict__ out,
                          const float* __restrict__ gs, const float* __restrict__ gb)
{
    int row  = blockIdx.x * 8 + threadIdx.y;
    int lane = threadIdx.x;
    const float* r = in + (long long)row * D_;
    float4 xv[4];
    #pragma unroll
    for (int j = 0; j < 4; j++)
        xv[j] = *reinterpret_cast<const float4*>(&r[(j * 32 + lane) * 4]);
    float s = 0.f;
    #pragma unroll
    for (int j = 0; j < 4; j++) s += xv[j].x + xv[j].y + xv[j].z + xv[j].w;
    #pragma unroll
    for (int o = 16; o; o >>= 1) s += __shfl_xor_sync(0xffffffffu, s, o);
    float mean = s * (1.0f / D_);
    float vs = 0.f;
    #pragma unroll
    for (int j = 0; j < 4; j++) {
        float a = xv[j].x - mean, b2 = xv[j].y - mean, c = xv[j].z - mean, d = xv[j].w - mean;
        vs += a * a + b2 * b2 + c * c + d * d;
    }
    #pragma unroll
    for (int o = 16; o; o >>= 1) vs += __shfl_xor_sync(0xffffffffu, vs, o);
    float rstd = rsqrtf(vs * (1.0f / D_) + 1e-5f);
    __half* w = out + (long long)row * D_;
    #pragma unroll
    for (int j = 0; j < 4; j++) {
        int c0 = (j * 32 + lane) * 4;
        float4 sv = *reinterpret_cast<const float4*>(&gs[c0]);
        float4 bv = *reinterpret_cast<const float4*>(&gb[c0]);
        float tx = (xv[j].x - mean) * rstd * sv.x + bv.x;
        float ty = (xv[j].y - mean) * rstd * sv.y + bv.y;
        float tz = (xv[j].z - mean) * rstd * sv.z + bv.z;
        float tw = (xv[j].w - mean) * rstd * sv.w + bv.w;
        st_perm_h2(w, c0,     tx, ty);
        st_perm_h2(w, c0 + 2, tz, tw);
    }
}

// ======================================================================
// fp16 MMA GEMM: 128-thread CTA, 4 warps of 64x32. 3-stage cp.async.
// ======================================================================
struct TGB { const __half* A; const __half* Bt; void* C; const float* bias;
             const float* resid; int flags; int ldc; int bxShift; };
struct TGArgs { TGB t[3]; };

__global__ void __launch_bounds__(128, 3) tgemm_kernel(TGArgs args)
{
    extern __shared__ char smc[];
    char* sA = smc;
    char* sB = smc + NSTG3 * ABYT;
    TGB tb = args.t[blockIdx.z];

    int tid = threadIdx.x, w = tid >> 5, lane = tid & 31;
    int g = lane >> 2, tig = lane & 3;
    int bx = blockIdx.x;
    int bn = (bx & ((1 << tb.bxShift) - 1)) * 64;
    int bm = (bx >> tb.bxShift) * 128;
    int wm = (w & 1) * 64, wn = (w >> 1) * 32;

    unsigned uA = (unsigned)__cvta_generic_to_shared(sA);
    unsigned uB = (unsigned)__cvta_generic_to_shared(sB);
    int crow = tid >> 3, cch = tid & 7;
    unsigned cxor = (unsigned)((cch * 16) ^ ((crow & 1) << 6));
    unsigned aBase = uA + (unsigned)(crow * 128) + cxor;
    unsigned bBase = uB + (unsigned)(crow * 128) + cxor;
    const __half* aSrc = tb.A  + (long long)(bm + crow) * D_ + cch * 8;
    const __half* bSrc = tb.Bt + (long long)(bn + crow) * D_ + cch * 8;

    FRAG_OFFSETS_W()

    float acc[4][4][4];
    #pragma unroll
    for (int i = 0; i < 4; i++)
        #pragma unroll
        for (int j = 0; j < 4; j++)
            #pragma unroll
            for (int q = 0; q < 4; q++) acc[i][j][q] = 0.f;

    #pragma unroll
    for (int s = 0; s < 2; s++) {
        #pragma unroll
        for (int i = 0; i < 8; i++)
            CP16(aBase + (unsigned)(s * ABYT + i * 2048), aSrc + i * 16 * D_ + s * 64);
        #pragma unroll
        for (int i = 0; i < 4; i++)
            CP16(bBase + (unsigned)(s * BBYT + i * 2048), bSrc + i * 16 * D_ + s * 64);
        CPCOMMIT();
    }

    const int NKT = D_ / 64;   // 8
    #pragma unroll
    for (int kt = 0; kt < NKT; kt++) {
        CPWAIT(1);
        __syncthreads();
        int s = kt % NSTG3;
        char* pA = sA + s * ABYT;
        char* pB = sB + s * BBYT;
        if (kt + 2 < NKT) {
            int rs = (kt + 2) % NSTG3;
            int ko = (kt + 2) * 64;
            #pragma unroll
            for (int i = 0; i < 8; i++)
                CP16(aBase + (unsigned)(rs * ABYT + i * 2048), aSrc + i * 16 * D_ + ko);
            #pragma unroll
            for (int i = 0; i < 4; i++)
                CP16(bBase + (unsigned)(rs * BBYT + i * 2048), bSrc + i * 16 * D_ + ko);
        }
        CPCOMMIT();
        MMA_SUB_W(pA, pB, 0u)
        MMA_SUB_W(pA, pB, 64u)
    }

    int flags = tb.flags, ldc = tb.ldc;
    #pragma unroll
    for (int mt = 0; mt < 4; mt++) {
        #pragma unroll
        for (int nt = 0; nt < 4; nt++) {
            int row0 = bm + wm + mt * 16 + g;
            int col  = bn + wn + nt * 8 + 2 * tig;
            float v00 = acc[mt][nt][0], v01 = acc[mt][nt][1];
            float v10 = acc[mt][nt][2], v11 = acc[mt][nt][3];
            if (flags & 4) {
                float b0 = tb.bias[row0], b1 = tb.bias[row0 + 8];
                v00 += b0; v01 += b0; v10 += b1; v11 += b1;
            } else {
                float2 bv = *reinterpret_cast<const float2*>(&tb.bias[col]);
                v00 += bv.x; v01 += bv.y; v10 += bv.x; v11 += bv.y;
            }
            if (flags & 1) {
                v00 = fmaxf(v00, 0.f); v01 = fmaxf(v01, 0.f);
                v10 = fmaxf(v10, 0.f); v11 = fmaxf(v11, 0.f);
            }
            if (tb.resid) {
                float2 r0 = *reinterpret_cast<const float2*>(
                    &tb.resid[(long long)row0 * ldc + col]);
                float2 r1 = *reinterpret_cast<const float2*>(
                    &tb.resid[(long long)(row0 + 8) * ldc + col]);
                v00 += r0.x; v01 += r0.y; v10 += r1.x; v11 += r1.y;
            }
            if (flags & 2) {
                __half* r0p = (__half*)tb.C + (long long)row0 * ldc;
                __half* r1p = (__half*)tb.C + (long long)(row0 + 8) * ldc;
                st_perm_h2(r0p, col, v00, v01);
                st_perm_h2(r1p, col, v10, v11);
            } else {
                float* Cf = (float*)tb.C;
                *reinterpret_cast<float2*>(&Cf[(long long)row0 * ldc + col]) =
                    make_float2(v00, v01);
                *reinterpret_cast<float2*>(&Cf[(long long)(row0 + 8) * ldc + col]) =
                    make_float2(v10, v11);
            }
        }
    }
}

// ======================================================================
// Fused QK^T + softmax: 256 threads, CTA = 64 q-rows x 256 key cols.
// Each warp: 64x32 block via wide-tile machinery. Output P half perm, pitch 256.
// ======================================================================
__global__ void __launch_bounds__(256, 2) qk_softmax_kernel(
    const __half* __restrict__ q, const __half* __restrict__ k, __half* __restrict__ P)
{
    __shared__ __align__(16) char sA[8192];    // 64 x 128B
    __shared__ __align__(16) char sB[32768];   // 256 x 128B
    __shared__ float sred[64][8];

    int z = blockIdx.z, b = z >> 3, h = z & 7;
    int bm = blockIdx.x * 64;
    int tid = threadIdx.x, w = tid >> 5, lane = tid & 31;
    int g = lane >> 2, tig = lane & 3;
    int wm = 0, wn = w * 32;

    unsigned uA = (unsigned)__cvta_generic_to_shared(sA);
    unsigned uB = (unsigned)__cvta_generic_to_shared(sB);

    {   // A: 2 cp/thread (64 rows); K: 8 cp/thread (256 rows)
        #pragma unroll
        for (int i = 0; i < 2; i++) {
            int idx = tid + i * 256;
            int row = idx >> 3, ch = idx & 7;
            unsigned cx = (unsigned)((ch * 16) ^ ((row & 1) << 6));
            CP16(uA + (unsigned)(row * 128) + cx,
                 q + (long long)(b * T_ + bm + row) * D_ + h * DK_ + ch * 8);
        }
        #pragma unroll
        for (int i = 0; i < 8; i++) {
            int idx = tid + i * 256;
            int br = idx >> 3, bch = idx & 7;
            unsigned bx2 = (unsigned)((bch * 16) ^ ((br & 1) << 6));
            CP16(uB + (unsigned)(br * 128) + bx2,
                 k + (long long)(b * T_ + br) * D_ + h * DK_ + bch * 8);
        }
    }
    CPCOMMIT();

    FRAG_OFFSETS_W()

    float acc[4][4][4];
    #pragma unroll
    for (int i = 0; i < 4; i++)
        #pragma unroll
        for (int j = 0; j < 4; j++)
            #pragma unroll
            for (int qq = 0; qq < 4; qq++) acc[i][j][qq] = 0.f;

    CPWAIT(0);
    __syncthreads();
    MMA_SUB_W(sA, sB, 0u)
    MMA_SUB_W(sA, sB, 64u)

    #pragma unroll
    for (int i = 0; i < 4; i++)
        #pragma unroll
        for (int j = 0; j < 4; j++)
            #pragma unroll
            for (int qq = 0; qq < 4; qq++) acc[i][j][qq] *= 0.125f;

    // pass 1: per-row max -> sred[row][w]
    #pragma unroll
    for (int rs = 0; rs < 8; rs++) {
        int mt = rs >> 1, hh = (rs & 1) * 2;
        float m = -3.0e38f;
        #pragma unroll
        for (int nt = 0; nt < 4; nt++)
            m = fmaxf(m, fmaxf(acc[mt][nt][hh], acc[mt][nt][hh + 1]));
        m = fmaxf(m, __shfl_xor_sync(0xffffffffu, m, 1));
        m = fmaxf(m, __shfl_xor_sync(0xffffffffu, m, 2));
        if (tig == 0) sred[mt * 16 + (rs & 1) * 8 + g][w] = m;
    }
    __syncthreads();
    // pass 2: exp + partial sums (max re-read transiently per slot)
    #pragma unroll
    for (int rs = 0; rs < 8; rs++) {
        int mt = rs >> 1, hh = (rs & 1) * 2;
        int rr = mt * 16 + (rs & 1) * 8 + g;
        float m = sred[rr][0];
        #pragma unroll
        for (int ww = 1; ww < 8; ww++) m = fmaxf(m, sred[rr][ww]);
        float s = 0.f;
        #pragma unroll
        for (int nt = 0; nt < 4; nt++) {
            float e0 = __expf(acc[mt][nt][hh]     - m);
            float e1 = __expf(acc[mt][nt][hh + 1] - m);
            acc[mt][nt][hh]     = e0;
            acc[mt][nt][hh + 1] = e1;
            s += e0 + e1;
        }
        s += __shfl_xor_sync(0xffffffffu, s, 1);
        s += __shfl_xor_sync(0xffffffffu, s, 2);
        __syncthreads();                    // all warps read maxes before overwrite
        if (tig == 0) sred[rr][w] = s;
    }
    __syncthreads();
    // pass 3: normalize + store (pitch 256)
    __half* Pz = P + (long long)z * T_ * T_;
    #pragma unroll
    for (int mt = 0; mt < 4; mt++) {
        int r0 = mt * 16 + g, r1 = mt * 16 + 8 + g;
        float s0 = sred[r0][0], s1 = sred[r1][0];
        #pragma unroll
        for (int ww = 1; ww < 8; ww++) { s0 += sred[r0][ww]; s1 += sred[r1][ww]; }
        float i0 = 1.0f / s0, i1 = 1.0f / s1;
        #pragma unroll
        for (int nt = 0; nt < 4; nt++) {
            int col = wn + nt * 8 + 2 * tig;
            st_perm_h2(Pz + (long long)(bm + r0) * T_, col,
                       acc[mt][nt][0] * i0, acc[mt][nt][1] * i0);
            st_perm_h2(Pz + (long long)(bm + r1) * T_, col,
                       acc[mt][nt][2] * i1, acc[mt][nt][3] * i1);
        }
    }
}

// ======================================================================
// PV fp16: 128-thread CTA, 4 warps of 64x32, 3 stages. K = 256.
// ======================================================================
__global__ void __launch_bounds__(128, 3) pv_kernel(
    const __half* __restrict__ Ph, const __half* __restrict__ vT, __half* __restrict__ O)
{
    extern __shared__ char smc[];
    char* sA = smc;
    char* sB = smc + NSTG3 * ABYT;

    int z = blockIdx.z, b = z >> 3, h = z & 7;
    int tid = threadIdx.x, w = tid >> 5, lane = tid & 31;
    int g = lane >> 2, tig = lane & 3;
    int bm = blockIdx.y * 128;
    int wm = (w & 1) * 64, wn = (w >> 1) * 32;

    unsigned uA = (unsigned)__cvta_generic_to_shared(sA);
    unsigned uB = (unsigned)__cvta_generic_to_shared(sB);
    int crow = tid >> 3, cch = tid & 7;
    unsigned cxor = (unsigned)((cch * 16) ^ ((crow & 1) << 6));
    unsigned aBase = uA + (unsigned)(crow * 128) + cxor;
    unsigned bBase = uB + (unsigned)(crow * 128) + cxor;
    const __half* aSrc = Ph + ((long long)z * T_ + bm + crow) * T_ + cch * 8;
    const __half* bSrc = vT + (long long)(h * DK_ + crow) * (B_ * T_) + b * T_ + cch * 8;

    FRAG_OFFSETS_W()

    float acc[4][4][4];
    #pragma unroll
    for (int i = 0; i < 4; i++)
        #pragma unroll
        for (int j = 0; j < 4; j++)
            #pragma unroll
            for (int q = 0; q < 4; q++) acc[i][j][q] = 0.f;

    #pragma unroll
    for (int s = 0; s < 2; s++) {
        #pragma unroll
        for (int i = 0; i < 8; i++)
            CP16(aBase + (unsigned)(s * ABYT + i * 2048), aSrc + i * 16 * T_ + s * 64);
        #pragma unroll
        for (int i = 0; i < 4; i++)
            CP16(bBase + (unsigned)(s * BBYT + i * 2048), bSrc + i * 16 * (B_ * T_) + s * 64);
        CPCOMMIT();
    }

    const int NKT = T_ / 64;   // 4
    #pragma unroll
    for (int kt = 0; kt < NKT; kt++) {
        CPWAIT(1);
        __syncthreads();
        int s = kt % NSTG3;
        char* pA = sA + s * ABYT;
        char* pB = sB + s * BBYT;
        if (kt + 2 < NKT) {
            int rs = (kt + 2) % NSTG3;
            int ko = (kt + 2) * 64;
            #pragma unroll
            for (int i = 0; i < 8; i++)
                CP16(aBase + (unsigned)(rs * ABYT + i * 2048), aSrc + i * 16 * T_ + ko);
            #pragma unroll
            for (int i = 0; i < 4; i++)
                CP16(bBase + (unsigned)(rs * BBYT + i * 2048), bSrc + i * 16 * (B_ * T_) + ko);
        }
        CPCOMMIT();
        MMA_SUB_W(pA, pB, 0u)
        MMA_SUB_W(pA, pB, 64u)
    }

    #pragma unroll
    for (int mt = 0; mt < 4; mt++)
        #pragma unroll
        for (int nt = 0; nt < 4; nt++) {
            int gr   = b * T_ + bm + wm + mt * 16 + g;
            int colg = h * DK_ + wn + nt * 8 + 2 * tig;
            st_perm_h2(O + (long long)gr * D_, colg, acc[mt][nt][0], acc[mt][nt][1]);
            st_perm_h2(O + (long long)(gr + 8) * D_, colg, acc[mt][nt][2], acc[mt][nt][3]);
        }
}

// ---------------- PVAM head: 5 query positions per block ----------------
__global__ void __launch_bounds__(256) pvam_kernel(
    const float* __restrict__ wf, const float* __restrict__ emb,
    const int* __restrict__ gwp, const float* __restrict__ fc1,
    float* __restrict__ out)
{
    __shared__ float s_wp[5][D_];
    __shared__ float s_f[D_];
    __shared__ float s_sc[5][T_];
    __shared__ float s_red[40];
    int mg = blockIdx.x * 5, b = blockIdx.y;
    int tid = threadIdx.x;
    for (int i = tid; i < 5 * D_; i += 256) {
        int j = i >> 9, c = i & (D_ - 1);
        s_wp[j][c] = emb[(long long)gwp[mg + j] * D_ + c];
    }
    for (int i = tid; i < D_; i += 256) s_f[i] = fc1[i];
    __syncthreads();

    const float* wr = wf + ((long long)b * T_ + tid) * D_;
    float sc[5] = {0.f, 0.f, 0.f, 0.f, 0.f};
    for (int c4 = 0; c4 < D_ / 4; c4++) {
        float4 wv = *reinterpret_cast<const float4*>(&wr[c4 * 4]);
        float4 fv = *reinterpret_cast<const float4*>(&s_f[c4 * 4]);
        #pragma unroll
        for (int j = 0; j < 5; j++) {
            float4 pv = *reinterpret_cast<const float4*>(&s_wp[j][c4 * 4]);
            sc[j] += tanh_fast(wv.x + pv.x) * fv.x;
            sc[j] += tanh_fast(wv.y + pv.y) * fv.y;
            sc[j] += tanh_fast(wv.z + pv.z) * fv.z;
            sc[j] += tanh_fast(wv.w + pv.w) * fv.w;
        }
    }

    int wid = tid >> 5, lane = tid & 31;
    #pragma unroll
    for (int j = 0; j < 5; j++) {
        float mv = sc[j];
        #pragma unroll
        for (int o = 16; o; o >>= 1) mv = fmaxf(mv, __shfl_xor_sync(0xffffffffu, mv, o));
        if (lane == 0) s_red[wid] = mv;
        __syncthreads();
        if (tid < 32) {
            float t = (tid < 8) ? s_red[tid] : -3.0e38f;
            #pragma unroll
            for (int o = 4; o; o >>= 1) t = fmaxf(t, __shfl_xor_sync(0xffffffffu, t, o));
            if (tid == 0) s_red[32] = t;
        }
        __syncthreads();
        float e = __expf(sc[j] - s_red[32]);
        float sv = e;
        #pragma unroll
        for (int o = 16; o; o >>= 1) sv += __shfl_xor_sync(0xffffffffu, sv, o);
        if (lane == 0) s_red[8 + wid] = sv;
        __syncthreads();
        if (tid < 32) {
            float t = (tid < 8) ? s_red[8 + tid] : 0.f;
            #pragma unroll
            for (int o = 4; o; o >>= 1) t += __shfl_xor_sync(0xffffffffu, t, o);
            if (tid == 0) s_red[33] = t;
        }
        __syncthreads();
        s_sc[j][tid] = e * (1.0f / s_red[33]);
        __syncthreads();
    }

    const float* base = wf + (long long)b * T_ * D_;
    int c0 = tid, c1 = tid + 256;
    float a0[5] = {0.f, 0.f, 0.f, 0.f, 0.f};
    float a1[5] = {0.f, 0.f, 0.f, 0.f, 0.f};
    #pragma unroll 4
    for (int t = 0; t < T_; t++) {
        float w0 = base[(long long)t * D_ + c0];
        float w1 = base[(long long)t * D_ + c1];
        #pragma unroll
        for (int j = 0; j < 5; j++) {
            float s = s_sc[j][t];
            a0[j] += s * w0;
            a1[j] += s * w1;
        }
    }
    #pragma unroll
    for (int j = 0; j < 5; j++) {
        long long ob = ((long long)b * ML_ + mg + j) * D_;
        out[ob + c0] = a0[j];
        out[ob + c1] = a1[j];
    }
}

// ---------------- host launcher ----------------
extern "C" void kernel_launch(void* const* d_in, const int* in_sizes, int n_in,
                              void* d_out, int out_size)
{
    const float* x    = (const float*)d_in[0];
    const int*   ewp  = (const int*)  d_in[1];
    const int*   gwp  = (const int*)  d_in[2];
    const float* pos  = (const float*)d_in[3];
    const float* ln1s = (const float*)d_in[4];
    const float* ln1b = (const float*)d_in[5];
    const float* Wq   = (const float*)d_in[6];
    const float* bq   = (const float*)d_in[7];
    const float* Wk   = (const float*)d_in[8];
    const float* bk   = (const float*)d_in[9];
    const float* Wv   = (const float*)d_in[10];
    const float* bv   = (const float*)d_in[11];
    const float* Wo   = (const float*)d_in[12];
    const float* bo   = (const float*)d_in[13];
    const float* ln2s = (const float*)d_in[14];
    const float* ln2b = (const float*)d_in[15];
    const float* W1   = (const float*)d_in[16];
    const float* b1   = (const float*)d_in[17];
    const float* W2   = (const float*)d_in[18];
    const float* b2   = (const float*)d_in[19];
    const float* lnfs = (const float*)d_in[20];
    const float* lnfb = (const float*)d_in[21];
    const float* fc0w = (const float*)d_in[22];
    const float* fc0b = (const float*)d_in[23];
    const float* emb  = (const float*)d_in[24];
    const float* fc1  = (const float*)d_in[25];

    static float *enc = nullptr, *tmp, *q, *k, *v, *o, *p, *wT;
    if (!enc) {
        cudaGetSymbolAddress((void**)&enc, g_enc);
        cudaGetSymbolAddress((void**)&tmp, g_tmp);
        cudaGetSymbolAddress((void**)&q,   g_q);
        cudaGetSymbolAddress((void**)&k,   g_k);
        cudaGetSymbolAddress((void**)&v,   g_v);
        cudaGetSymbolAddress((void**)&o,   g_o);
        cudaGetSymbolAddress((void**)&p,   g_p);
        cudaGetSymbolAddress((void**)&wT,  g_wT);
        cudaFuncSetAttribute(tgemm_kernel,
                             cudaFuncAttributeMaxDynamicSharedMemorySize, TG_SMEM3);
        cudaFuncSetAttribute(pv_kernel,
                             cudaFuncAttributeMaxDynamicSharedMemorySize, TG_SMEM3);
    }

    __half* tmp_h = (__half*)tmp;
    __half* q_h   = (__half*)q;
    __half* k_h   = (__half*)k;
    __half* v_h   = (__half*)v;
    __half* o_h   = (__half*)o;
    __half* p_h   = (__half*)p;
    __half* wT_h  = (__half*)wT;

    const long long DD = (long long)D_ * D_;

    WP wp;
    wp.w[0]  = Wq;       wp.w[1]  = Wk;       wp.w[2]  = Wv;
    wp.w[3]  = Wo;       wp.w[4]  = W1;       wp.w[5]  = W2;
    wp.w[6]  = Wq + DD;  wp.w[7]  = Wk + DD;  wp.w[8]  = Wv + DD;
    wp.w[9]  = Wo + DD;  wp.w[10] = W1 + DD;  wp.w[11] = W2 + DD;
    wp.w[12] = fc0w;
    wtrans_kernel<<<dim3(16, 16, NWMAT), dim3(32, 8)>>>(wp, wT_h);

    prep_kernel<<<dim3(D_ / 32, T_ / 32, B_), dim3(32, 8)>>>(x, pos, ewp, enc);

    const int MT = B_ * T_;   // 8192

    for (int l = 0; l < L_; l++) {
        int vo = l * D_;
        const __half* wq = wT_h + (l * 6 + 0) * DD;
        const __half* wk = wT_h + (l * 6 + 1) * DD;
        const __half* wv = wT_h + (l * 6 + 2) * DD;
        const __half* wo = wT_h + (l * 6 + 3) * DD;
        const __half* w1 = wT_h + (l * 6 + 4) * DD;
        const __half* w2 = wT_h + (l * 6 + 5) * DD;

        ln_kernel<<<MT / 8, dim3(32, 8)>>>(enc, tmp_h, ln1s + vo, ln1b + vo);

        TGArgs aqkv;
        aqkv.t[0] = {tmp_h, wq, q_h, bq + vo, nullptr, 2, D_, 3};
        aqkv.t[1] = {tmp_h, wk, k_h, bk + vo, nullptr, 2, D_, 3};
        aqkv.t[2] = {wv, tmp_h, v_h, bv + vo, nullptr, 2 | 4, MT, 7};
        tgemm_kernel<<<dim3(512, 1, 3), 128, TG_SMEM3>>>(aqkv);

        qk_softmax_kernel<<<dim3(T_ / 64, 1, B_ * NH_), 256>>>(q_h, k_h, p_h);
        pv_kernel<<<dim3(1, T_ / 128, B_ * NH_), 128, TG_SMEM3>>>(p_h, v_h, o_h);

        TGArgs ao; ao.t[0] = {o_h, wo, enc, bo + vo, enc, 0, D_, 3};
        tgemm_kernel<<<dim3(512, 1, 1), 128, TG_SMEM3>>>(ao);

        ln_kernel<<<MT / 8, dim3(32, 8)>>>(enc, tmp_h, ln2s + vo, ln2b + vo);
        TGArgs a1; a1.t[0] = {tmp_h, w1, o_h, b1 + vo, nullptr, 3, D_, 3};
        tgemm_kernel<<<dim3(512, 1, 1), 128, TG_SMEM3>>>(a1);
        TGArgs a2; a2.t[0] = {o_h, w2, enc, b2 + vo, enc, 0, D_, 3};
        tgemm_kernel<<<dim3(512, 1, 1), 128, TG_SMEM3>>>(a2);
    }

    ln_kernel<<<MT / 8, dim3(32, 8)>>>(enc, tmp_h, lnfs, lnfb);
    TGArgs af; af.t[0] = {tmp_h, wT_h + 12 * DD, q, fc0b, nullptr, 0, D_, 3};
    tgemm_kernel<<<dim3(512, 1, 1), 128, TG_SMEM3>>>(af);

    pvam_kernel<<<dim3(ML_ / 5, B_), 256>>>(q, emb, gwp, fc1, (float*)d_out);
}

// round 14
// speedup vs baseline: 1.0190x; 1.0067x over previous
#include <cuda_runtime.h>
#include <cuda_fp16.h>
#include <math.h>

// ---------------- problem constants ----------------
#define B_  32
#define T_  256
#define D_  512
#define NH_ 8
#define DK_ 64
#define L_  2
#define ML_ 25
#define NWMAT 13

// ---------------- scratch ----------------
__device__ float g_enc[B_*T_*D_];
__device__ float g_tmp[B_*T_*D_];
__device__ float g_q  [B_*T_*D_];
__device__ float g_k  [B_*T_*D_];
__device__ float g_v  [B_*T_*D_];   // V^T halves [512, 8192]
__device__ float g_o  [B_*T_*D_];
__device__ float g_p  [B_*NH_*T_*T_];  // P halves, pitch 256
__device__ float g_wT [NWMAT*D_*D_];   // halves, perm layout

__device__ __forceinline__ float tanh_fast(float x) {
    float y;
    asm("tanh.approx.f32 %0, %1;" : "=f"(y) : "f"(x));
    return y;
}
__device__ __forceinline__ int pidx32(int k) {
    return ((k & 6) >> 1) * 8 + ((k >> 4) & 1) * 4 + ((k >> 3) & 1) * 2 + (k & 1);
}
__device__ __forceinline__ void st_perm_h2(__half* rowp, int c, float v0, float v1) {
    *reinterpret_cast<__half2*>(&rowp[(c & ~31) + pidx32(c & 31)]) = __floats2half2_rn(v0, v1);
}

#define CP16(dst, src) \
    asm volatile("cp.async.cg.shared.global [%0], [%1], 16;" :: "r"(dst), "l"(src) : "memory")
#define CPCOMMIT() asm volatile("cp.async.commit_group;" ::: "memory")
#define CPWAIT(n)  asm volatile("cp.async.wait_group %0;" :: "n"(n) : "memory")

__device__ __forceinline__ void mma_f16(float c[4],
                                        unsigned a0, unsigned a1, unsigned a2, unsigned a3,
                                        unsigned b0, unsigned b1)
{
    asm volatile(
        "mma.sync.aligned.m16n8k16.row.col.f32.f16.f16.f32 "
        "{%0,%1,%2,%3}, {%4,%5,%6,%7}, {%8,%9}, {%0,%1,%2,%3};"
        : "+f"(c[0]), "+f"(c[1]), "+f"(c[2]), "+f"(c[3])
        : "r"(a0), "r"(a1), "r"(a2), "r"(a3), "r"(b0), "r"(b1));
}

// ---------------- tiling ----------------
#define ABYT 16384
#define BBYT 8192
#define NSTG3 3
#define TG_SMEM3 (NSTG3 * (ABYT + BBYT))   // 73728

// ===== wide warp tile (64x32) fragment machinery =====
#define FRAG_OFFSETS_W()                                                              \
    unsigned paL[8], pbL[4];                                                          \
    _Pragma("unroll")                                                                 \
    for (int r2 = 0; r2 < 8; r2++) {                                                  \
        int row = wm + r2 * 8 + g;                                                    \
        paL[r2] = (unsigned)(row * 128 + tig * 16 + ((row & 1) << 6));                \
    }                                                                                 \
    _Pragma("unroll")                                                                 \
    for (int r2 = 0; r2 < 4; r2++) {                                                  \
        int rob = wn + r2 * 8 + g;                                                    \
        pbL[r2] = (unsigned)(rob * 128 + tig * 16 + ((rob & 1) << 6));                \
    }

#define MMA_SUB_W(stgA, stgB, XORV) {                                                 \
    uint4 aU[8], bU[4];                                                               \
    _Pragma("unroll")                                                                 \
    for (int r2 = 0; r2 < 8; r2++)                                                    \
        aU[r2] = *reinterpret_cast<const uint4*>((stgA) + (paL[r2] ^ (XORV)));        \
    _Pragma("unroll")                                                                 \
    for (int r2 = 0; r2 < 4; r2++)                                                    \
        bU[r2] = *reinterpret_cast<const uint4*>((stgB) + (pbL[r2] ^ (XORV)));        \
    _Pragma("unroll")                                                                 \
    for (int mt = 0; mt < 4; mt++)                                                    \
        _Pragma("unroll")                                                             \
        for (int nt = 0; nt < 4; nt++) {                                              \
            mma_f16(acc[mt][nt], aU[2*mt].x, aU[2*mt+1].x, aU[2*mt].y, aU[2*mt+1].y,  \
                    bU[nt].x, bU[nt].y);                                              \
            mma_f16(acc[mt][nt], aU[2*mt].z, aU[2*mt+1].z, aU[2*mt].w, aU[2*mt+1].w,  \
                    bU[nt].z, bU[nt].w);                                              \
        }                                                                             \
}

// ---------------- prep ----------------
__global__ void prep_kernel(const float* __restrict__ x, const float* __restrict__ pos,
                            const int* __restrict__ ewp, float* __restrict__ enc)
{
    __shared__ float tile[32][33];
    int b  = blockIdx.z;
    int d0 = blockIdx.x * 32, t0 = blockIdx.y * 32;
    int tx = threadIdx.x, ty = threadIdx.y;
    const float* xb = x + (long long)b * D_ * T_;
    #pragma unroll
    for (int i = 0; i < 4; i++) {
        int d = ty + i * 8;
        tile[d][tx] = xb[(long long)(d0 + d) * T_ + t0 + tx];
    }
    __syncthreads();
    #pragma unroll
    for (int i = 0; i < 4; i++) {
        int tl = ty + i * 8;
        int t = t0 + tl, d = d0 + tx;
        int pr = ewp[t];
        enc[(((long long)b * T_) + t) * D_ + d] =
            tile[tx][tl] * 22.62741699796952f + pos[(long long)pr * D_ + d];
    }
}

// ---------------- weight transpose -> half perm ----------------
struct WP { const float* w[NWMAT]; };
__global__ void wtrans_kernel(WP p, __half* __restrict__ out)
{
    __shared__ float t[32][33];
    int mi = blockIdx.z;
    const float* W = p.w[mi];
    __half* O = out + (long long)mi * D_ * D_;
    int n0 = blockIdx.x * 32, k0 = blockIdx.y * 32;
    int tx = threadIdx.x, ty = threadIdx.y;
    #pragma unroll
    for (int i = 0; i < 4; i++) {
        int k = k0 + ty + i * 8;
        t[ty + i * 8][tx] = W[(long long)k * D_ + n0 + tx];
    }
    __syncthreads();
    #pragma unroll
    for (int i = 0; i < 4; i++) {
        int n = n0 + ty + i * 8;
        O[(long long)n * D_ + k0 + pidx32(tx)] = __float2half(t[tx][ty + i * 8]);
    }
}

// ---------------- layernorm -> half perm ----------------
__global__ void ln_kernel(const float* __restrict__ in, __half* __restrict__ out,
                          const float* __restrict__ gs, const float* __restrict__ gb)
{
    int row  = blockIdx.x * 8 + threadIdx.y;
    int lane = threadIdx.x;
    const float* r = in + (long long)row * D_;
    float4 xv[4];
    #pragma unroll
    for (int j = 0; j < 4; j++)
        xv[j] = *reinterpret_cast<const float4*>(&r[(j * 32 + lane) * 4]);
    float s = 0.f;
    #pragma unroll
    for (int j = 0; j < 4; j++) s += xv[j].x + xv[j].y + xv[j].z + xv[j].w;
    #pragma unroll
    for (int o = 16; o; o >>= 1) s += __shfl_xor_sync(0xffffffffu, s, o);
    float mean = s * (1.0f / D_);
    float vs = 0.f;
    #pragma unroll
    for (int j = 0; j < 4; j++) {
        float a = xv[j].x - mean, b2 = xv[j].y - mean, c = xv[j].z - mean, d = xv[j].w - mean;
        vs += a * a + b2 * b2 + c * c + d * d;
    }
    #pragma unroll
    for (int o = 16; o; o >>= 1) vs += __shfl_xor_sync(0xffffffffu, vs, o);
    float rstd = rsqrtf(vs * (1.0f / D_) + 1e-5f);
    __half* w = out + (long long)row * D_;
    #pragma unroll
    for (int j = 0; j < 4; j++) {
        int c0 = (j * 32 + lane) * 4;
        float4 sv = *reinterpret_cast<const float4*>(&gs[c0]);
        float4 bv = *reinterpret_cast<const float4*>(&gb[c0]);
        float tx = (xv[j].x - mean) * rstd * sv.x + bv.x;
        float ty = (xv[j].y - mean) * rstd * sv.y + bv.y;
        float tz = (xv[j].z - mean) * rstd * sv.z + bv.z;
        float tw = (xv[j].w - mean) * rstd * sv.w + bv.w;
        st_perm_h2(w, c0,     tx, ty);
        st_perm_h2(w, c0 + 2, tz, tw);
    }
}

// ======================================================================
// fp16 MMA GEMM: 128-thread CTA, 4 warps of 64x32. 3-stage cp.async.
// ======================================================================
struct TGB { const __half* A; const __half* Bt; void* C; const float* bias;
             const float* resid; int flags; int ldc; int bxShift; };
struct TGArgs { TGB t[3]; };

__global__ void __launch_bounds__(128, 3) tgemm_kernel(TGArgs args)
{
    extern __shared__ char smc[];
    char* sA = smc;
    char* sB = smc + NSTG3 * ABYT;
    TGB tb = args.t[blockIdx.z];

    int tid = threadIdx.x, w = tid >> 5, lane = tid & 31;
    int g = lane >> 2, tig = lane & 3;
    int bx = blockIdx.x;
    int bn = (bx & ((1 << tb.bxShift) - 1)) * 64;
    int bm = (bx >> tb.bxShift) * 128;
    int wm = (w & 1) * 64, wn = (w >> 1) * 32;

    unsigned uA = (unsigned)__cvta_generic_to_shared(sA);
    unsigned uB = (unsigned)__cvta_generic_to_shared(sB);
    int crow = tid >> 3, cch = tid & 7;
    unsigned cxor = (unsigned)((cch * 16) ^ ((crow & 1) << 6));
    unsigned aBase = uA + (unsigned)(crow * 128) + cxor;
    unsigned bBase = uB + (unsigned)(crow * 128) + cxor;
    const __half* aSrc = tb.A  + (long long)(bm + crow) * D_ + cch * 8;
    const __half* bSrc = tb.Bt + (long long)(bn + crow) * D_ + cch * 8;

    FRAG_OFFSETS_W()

    float acc[4][4][4];
    #pragma unroll
    for (int i = 0; i < 4; i++)
        #pragma unroll
        for (int j = 0; j < 4; j++)
            #pragma unroll
            for (int q = 0; q < 4; q++) acc[i][j][q] = 0.f;

    #pragma unroll
    for (int s = 0; s < 2; s++) {
        #pragma unroll
        for (int i = 0; i < 8; i++)
            CP16(aBase + (unsigned)(s * ABYT + i * 2048), aSrc + i * 16 * D_ + s * 64);
        #pragma unroll
        for (int i = 0; i < 4; i++)
            CP16(bBase + (unsigned)(s * BBYT + i * 2048), bSrc + i * 16 * D_ + s * 64);
        CPCOMMIT();
    }

    const int NKT = D_ / 64;   // 8
    #pragma unroll
    for (int kt = 0; kt < NKT; kt++) {
        CPWAIT(1);
        __syncthreads();
        int s = kt % NSTG3;
        char* pA = sA + s * ABYT;
        char* pB = sB + s * BBYT;
        if (kt + 2 < NKT) {
            int rs = (kt + 2) % NSTG3;
            int ko = (kt + 2) * 64;
            #pragma unroll
            for (int i = 0; i < 8; i++)
                CP16(aBase + (unsigned)(rs * ABYT + i * 2048), aSrc + i * 16 * D_ + ko);
            #pragma unroll
            for (int i = 0; i < 4; i++)
                CP16(bBase + (unsigned)(rs * BBYT + i * 2048), bSrc + i * 16 * D_ + ko);
        }
        CPCOMMIT();
        MMA_SUB_W(pA, pB, 0u)
        MMA_SUB_W(pA, pB, 64u)
    }

    int flags = tb.flags, ldc = tb.ldc;
    #pragma unroll
    for (int mt = 0; mt < 4; mt++) {
        #pragma unroll
        for (int nt = 0; nt < 4; nt++) {
            int row0 = bm + wm + mt * 16 + g;
            int col  = bn + wn + nt * 8 + 2 * tig;
            float v00 = acc[mt][nt][0], v01 = acc[mt][nt][1];
            float v10 = acc[mt][nt][2], v11 = acc[mt][nt][3];
            if (flags & 4) {
                float b0 = tb.bias[row0], b1 = tb.bias[row0 + 8];
                v00 += b0; v01 += b0; v10 += b1; v11 += b1;
            } else {
                float2 bv = *reinterpret_cast<const float2*>(&tb.bias[col]);
                v00 += bv.x; v01 += bv.y; v10 += bv.x; v11 += bv.y;
            }
            if (flags & 1) {
                v00 = fmaxf(v00, 0.f); v01 = fmaxf(v01, 0.f);
                v10 = fmaxf(v10, 0.f); v11 = fmaxf(v11, 0.f);
            }
            if (tb.resid) {
                float2 r0 = *reinterpret_cast<const float2*>(
                    &tb.resid[(long long)row0 * ldc + col]);
                float2 r1 = *reinterpret_cast<const float2*>(
                    &tb.resid[(long long)(row0 + 8) * ldc + col]);
                v00 += r0.x; v01 += r0.y; v10 += r1.x; v11 += r1.y;
            }
            if (flags & 2) {
                __half* r0p = (__half*)tb.C + (long long)row0 * ldc;
                __half* r1p = (__half*)tb.C + (long long)(row0 + 8) * ldc;
                st_perm_h2(r0p, col, v00, v01);
                st_perm_h2(r1p, col, v10, v11);
            } else {
                float* Cf = (float*)tb.C;
                *reinterpret_cast<float2*>(&Cf[(long long)row0 * ldc + col]) =
                    make_float2(v00, v01);
                *reinterpret_cast<float2*>(&Cf[(long long)(row0 + 8) * ldc + col]) =
                    make_float2(v10, v11);
            }
        }
    }
}

// ======================================================================
// Fused QK^T + softmax: 256 threads, CTA = 64 q-rows x 256 key cols.
// ======================================================================
__global__ void __launch_bounds__(256, 2) qk_softmax_kernel(
    const __half* __restrict__ q, const __half* __restrict__ k, __half* __restrict__ P)
{
    __shared__ __align__(16) char sA[8192];    // 64 x 128B
    __shared__ __align__(16) char sB[32768];   // 256 x 128B
    __shared__ float sred[64][8];

    int z = blockIdx.z, b = z >> 3, h = z & 7;
    int bm = blockIdx.x * 64;
    int tid = threadIdx.x, w = tid >> 5, lane = tid & 31;
    int g = lane >> 2, tig = lane & 3;
    int wm = 0, wn = w * 32;

    unsigned uA = (unsigned)__cvta_generic_to_shared(sA);
    unsigned uB = (unsigned)__cvta_generic_to_shared(sB);

    {
        #pragma unroll
        for (int i = 0; i < 2; i++) {
            int idx = tid + i * 256;
            int row = idx >> 3, ch = idx & 7;
            unsigned cx = (unsigned)((ch * 16) ^ ((row & 1) << 6));
            CP16(uA + (unsigned)(row * 128) + cx,
                 q + (long long)(b * T_ + bm + row) * D_ + h * DK_ + ch * 8);
        }
        #pragma unroll
        for (int i = 0; i < 8; i++) {
            int idx = tid + i * 256;
            int br = idx >> 3, bch = idx & 7;
            unsigned bx2 = (unsigned)((bch * 16) ^ ((br & 1) << 6));
            CP16(uB + (unsigned)(br * 128) + bx2,
                 k + (long long)(b * T_ + br) * D_ + h * DK_ + bch * 8);
        }
    }
    CPCOMMIT();

    FRAG_OFFSETS_W()

    float acc[4][4][4];
    #pragma unroll
    for (int i = 0; i < 4; i++)
        #pragma unroll
        for (int j = 0; j < 4; j++)
            #pragma unroll
            for (int qq = 0; qq < 4; qq++) acc[i][j][qq] = 0.f;

    CPWAIT(0);
    __syncthreads();
    MMA_SUB_W(sA, sB, 0u)
    MMA_SUB_W(sA, sB, 64u)

    #pragma unroll
    for (int i = 0; i < 4; i++)
        #pragma unroll
        for (int j = 0; j < 4; j++)
            #pragma unroll
            for (int qq = 0; qq < 4; qq++) acc[i][j][qq] *= 0.125f;

    #pragma unroll
    for (int rs = 0; rs < 8; rs++) {
        int mt = rs >> 1, hh = (rs & 1) * 2;
        float m = -3.0e38f;
        #pragma unroll
        for (int nt = 0; nt < 4; nt++)
            m = fmaxf(m, fmaxf(acc[mt][nt][hh], acc[mt][nt][hh + 1]));
        m = fmaxf(m, __shfl_xor_sync(0xffffffffu, m, 1));
        m = fmaxf(m, __shfl_xor_sync(0xffffffffu, m, 2));
        if (tig == 0) sred[mt * 16 + (rs & 1) * 8 + g][w] = m;
    }
    __syncthreads();
    #pragma unroll
    for (int rs = 0; rs < 8; rs++) {
        int mt = rs >> 1, hh = (rs & 1) * 2;
        int rr = mt * 16 + (rs & 1) * 8 + g;
        float m = sred[rr][0];
        #pragma unroll
        for (int ww = 1; ww < 8; ww++) m = fmaxf(m, sred[rr][ww]);
        float s = 0.f;
        #pragma unroll
        for (int nt = 0; nt < 4; nt++) {
            float e0 = __expf(acc[mt][nt][hh]     - m);
            float e1 = __expf(acc[mt][nt][hh + 1] - m);
            acc[mt][nt][hh]     = e0;
            acc[mt][nt][hh + 1] = e1;
            s += e0 + e1;
        }
        s += __shfl_xor_sync(0xffffffffu, s, 1);
        s += __shfl_xor_sync(0xffffffffu, s, 2);
        __syncthreads();
        if (tig == 0) sred[rr][w] = s;
    }
    __syncthreads();
    __half* Pz = P + (long long)z * T_ * T_;
    #pragma unroll
    for (int mt = 0; mt < 4; mt++) {
        int r0 = mt * 16 + g, r1 = mt * 16 + 8 + g;
        float s0 = sred[r0][0], s1 = sred[r1][0];
        #pragma unroll
        for (int ww = 1; ww < 8; ww++) { s0 += sred[r0][ww]; s1 += sred[r1][ww]; }
        float i0 = 1.0f / s0, i1 = 1.0f / s1;
        #pragma unroll
        for (int nt = 0; nt < 4; nt++) {
            int col = wn + nt * 8 + 2 * tig;
            st_perm_h2(Pz + (long long)(bm + r0) * T_, col,
                       acc[mt][nt][0] * i0, acc[mt][nt][1] * i0);
            st_perm_h2(Pz + (long long)(bm + r1) * T_, col,
                       acc[mt][nt][2] * i1, acc[mt][nt][3] * i1);
        }
    }
}

// ======================================================================
// PV fp16: 128-thread CTA, 4 warps of 64x32, 3 stages. K = 256.
// ======================================================================
__global__ void __launch_bounds__(128, 3) pv_kernel(
    const __half* __restrict__ Ph, const __half* __restrict__ vT, __half* __restrict__ O)
{
    extern __shared__ char smc[];
    char* sA = smc;
    char* sB = smc + NSTG3 * ABYT;

    int z = blockIdx.z, b = z >> 3, h = z & 7;
    int tid = threadIdx.x, w = tid >> 5, lane = tid & 31;
    int g = lane >> 2, tig = lane & 3;
    int bm = blockIdx.y * 128;
    int wm = (w & 1) * 64, wn = (w >> 1) * 32;

    unsigned uA = (unsigned)__cvta_generic_to_shared(sA);
    unsigned uB = (unsigned)__cvta_generic_to_shared(sB);
    int crow = tid >> 3, cch = tid & 7;
    unsigned cxor = (unsigned)((cch * 16) ^ ((crow & 1) << 6));
    unsigned aBase = uA + (unsigned)(crow * 128) + cxor;
    unsigned bBase = uB + (unsigned)(crow * 128) + cxor;
    const __half* aSrc = Ph + ((long long)z * T_ + bm + crow) * T_ + cch * 8;
    const __half* bSrc = vT + (long long)(h * DK_ + crow) * (B_ * T_) + b * T_ + cch * 8;

    FRAG_OFFSETS_W()

    float acc[4][4][4];
    #pragma unroll
    for (int i = 0; i < 4; i++)
        #pragma unroll
        for (int j = 0; j < 4; j++)
            #pragma unroll
            for (int q = 0; q < 4; q++) acc[i][j][q] = 0.f;

    #pragma unroll
    for (int s = 0; s < 2; s++) {
        #pragma unroll
        for (int i = 0; i < 8; i++)
            CP16(aBase + (unsigned)(s * ABYT + i * 2048), aSrc + i * 16 * T_ + s * 64);
        #pragma unroll
        for (int i = 0; i < 4; i++)
            CP16(bBase + (unsigned)(s * BBYT + i * 2048), bSrc + i * 16 * (B_ * T_) + s * 64);
        CPCOMMIT();
    }

    const int NKT = T_ / 64;   // 4
    #pragma unroll
    for (int kt = 0; kt < NKT; kt++) {
        CPWAIT(1);
        __syncthreads();
        int s = kt % NSTG3;
        char* pA = sA + s * ABYT;
        char* pB = sB + s * BBYT;
        if (kt + 2 < NKT) {
            int rs = (kt + 2) % NSTG3;
            int ko = (kt + 2) * 64;
            #pragma unroll
            for (int i = 0; i < 8; i++)
                CP16(aBase + (unsigned)(rs * ABYT + i * 2048), aSrc + i * 16 * T_ + ko);
            #pragma unroll
            for (int i = 0; i < 4; i++)
                CP16(bBase + (unsigned)(rs * BBYT + i * 2048), bSrc + i * 16 * (B_ * T_) + ko);
        }
        CPCOMMIT();
        MMA_SUB_W(pA, pB, 0u)
        MMA_SUB_W(pA, pB, 64u)
    }

    #pragma unroll
    for (int mt = 0; mt < 4; mt++)
        #pragma unroll
        for (int nt = 0; nt < 4; nt++) {
            int gr   = b * T_ + bm + wm + mt * 16 + g;
            int colg = h * DK_ + wn + nt * 8 + 2 * tig;
            st_perm_h2(O + (long long)gr * D_, colg, acc[mt][nt][0], acc[mt][nt][1]);
            st_perm_h2(O + (long long)(gr + 8) * D_, colg, acc[mt][nt][2], acc[mt][nt][3]);
        }
}

// ---------------- PVAM head: 5 query positions per block ----------------
__global__ void __launch_bounds__(256) pvam_kernel(
    const float* __restrict__ wf, const float* __restrict__ emb,
    const int* __restrict__ gwp, const float* __restrict__ fc1,
    float* __restrict__ out)
{
    __shared__ float s_wp[5][D_];
    __shared__ float s_f[D_];
    __shared__ float s_sc[5][T_];
    __shared__ float s_red[40];
    int mg = blockIdx.x * 5, b = blockIdx.y;
    int tid = threadIdx.x;
    for (int i = tid; i < 5 * D_; i += 256) {
        int j = i >> 9, c = i & (D_ - 1);
        s_wp[j][c] = emb[(long long)gwp[mg + j] * D_ + c];
    }
    for (int i = tid; i < D_; i += 256) s_f[i] = fc1[i];
    __syncthreads();

    const float* wr = wf + ((long long)b * T_ + tid) * D_;
    float sc[5] = {0.f, 0.f, 0.f, 0.f, 0.f};
    for (int c4 = 0; c4 < D_ / 4; c4++) {
        float4 wv = *reinterpret_cast<const float4*>(&wr[c4 * 4]);
        float4 fv = *reinterpret_cast<const float4*>(&s_f[c4 * 4]);
        #pragma unroll
        for (int j = 0; j < 5; j++) {
            float4 pv = *reinterpret_cast<const float4*>(&s_wp[j][c4 * 4]);
            sc[j] += tanh_fast(wv.x + pv.x) * fv.x;
            sc[j] += tanh_fast(wv.y + pv.y) * fv.y;
            sc[j] += tanh_fast(wv.z + pv.z) * fv.z;
            sc[j] += tanh_fast(wv.w + pv.w) * fv.w;
        }
    }

    int wid = tid >> 5, lane = tid & 31;
    #pragma unroll
    for (int j = 0; j < 5; j++) {
        float mv = sc[j];
        #pragma unroll
        for (int o = 16; o; o >>= 1) mv = fmaxf(mv, __shfl_xor_sync(0xffffffffu, mv, o));
        if (lane == 0) s_red[wid] = mv;
        __syncthreads();
        if (tid < 32) {
            float t = (tid < 8) ? s_red[tid] : -3.0e38f;
            #pragma unroll
            for (int o = 4; o; o >>= 1) t = fmaxf(t, __shfl_xor_sync(0xffffffffu, t, o));
            if (tid == 0) s_red[32] = t;
        }
        __syncthreads();
        float e = __expf(sc[j] - s_red[32]);
        float sv = e;
        #pragma unroll
        for (int o = 16; o; o >>= 1) sv += __shfl_xor_sync(0xffffffffu, sv, o);
        if (lane == 0) s_red[8 + wid] = sv;
        __syncthreads();
        if (tid < 32) {
            float t = (tid < 8) ? s_red[8 + tid] : 0.f;
            #pragma unroll
            for (int o = 4; o; o >>= 1) t += __shfl_xor_sync(0xffffffffu, t, o);
            if (tid == 0) s_red[33] = t;
        }
        __syncthreads();
        s_sc[j][tid] = e * (1.0f / s_red[33]);
        __syncthreads();
    }

    const float* base = wf + (long long)b * T_ * D_;
    int c0 = tid, c1 = tid + 256;
    float a0[5] = {0.f, 0.f, 0.f, 0.f, 0.f};
    float a1[5] = {0.f, 0.f, 0.f, 0.f, 0.f};
    #pragma unroll 4
    for (int t = 0; t < T_; t++) {
        float w0 = base[(long long)t * D_ + c0];
        float w1 = base[(long long)t * D_ + c1];
        #pragma unroll
        for (int j = 0; j < 5; j++) {
            float s = s_sc[j][t];
            a0[j] += s * w0;
            a1[j] += s * w1;
        }
    }
    #pragma unroll
    for (int j = 0; j < 5; j++) {
        long long ob = ((long long)b * ML_ + mg + j) * D_;
        out[ob + c0] = a0[j];
        out[ob + c1] = a1[j];
    }
}

// ---------------- host launcher (fork/join streams inside capture) ----------------
extern "C" void kernel_launch(void* const* d_in, const int* in_sizes, int n_in,
                              void* d_out, int out_size)
{
    const float* x    = (const float*)d_in[0];
    const int*   ewp  = (const int*)  d_in[1];
    const int*   gwp  = (const int*)  d_in[2];
    const float* pos  = (const float*)d_in[3];
    const float* ln1s = (const float*)d_in[4];
    const float* ln1b = (const float*)d_in[5];
    const float* Wq   = (const float*)d_in[6];
    const float* bq   = (const float*)d_in[7];
    const float* Wk   = (const float*)d_in[8];
    const float* bk   = (const float*)d_in[9];
    const float* Wv   = (const float*)d_in[10];
    const float* bv   = (const float*)d_in[11];
    const float* Wo   = (const float*)d_in[12];
    const float* bo   = (const float*)d_in[13];
    const float* ln2s = (const float*)d_in[14];
    const float* ln2b = (const float*)d_in[15];
    const float* W1   = (const float*)d_in[16];
    const float* b1   = (const float*)d_in[17];
    const float* W2   = (const float*)d_in[18];
    const float* b2   = (const float*)d_in[19];
    const float* lnfs = (const float*)d_in[20];
    const float* lnfb = (const float*)d_in[21];
    const float* fc0w = (const float*)d_in[22];
    const float* fc0b = (const float*)d_in[23];
    const float* emb  = (const float*)d_in[24];
    const float* fc1  = (const float*)d_in[25];

    static float *enc = nullptr, *tmp, *q, *k, *v, *o, *p, *wT;
    static cudaStream_t s1 = nullptr;
    static cudaEvent_t ev[8];
    if (!enc) {
        cudaGetSymbolAddress((void**)&enc, g_enc);
        cudaGetSymbolAddress((void**)&tmp, g_tmp);
        cudaGetSymbolAddress((void**)&q,   g_q);
        cudaGetSymbolAddress((void**)&k,   g_k);
        cudaGetSymbolAddress((void**)&v,   g_v);
        cudaGetSymbolAddress((void**)&o,   g_o);
        cudaGetSymbolAddress((void**)&p,   g_p);
        cudaGetSymbolAddress((void**)&wT,  g_wT);
        cudaFuncSetAttribute(tgemm_kernel,
                             cudaFuncAttributeMaxDynamicSharedMemorySize, TG_SMEM3);
        cudaFuncSetAttribute(pv_kernel,
                             cudaFuncAttributeMaxDynamicSharedMemorySize, TG_SMEM3);
        cudaStreamCreateWithFlags(&s1, cudaStreamNonBlocking);
        for (int i = 0; i < 8; i++)
            cudaEventCreateWithFlags(&ev[i], cudaEventDisableTiming);
    }

    __half* tmp_h = (__half*)tmp;
    __half* q_h   = (__half*)q;
    __half* k_h   = (__half*)k;
    __half* v_h   = (__half*)v;
    __half* o_h   = (__half*)o;
    __half* p_h   = (__half*)p;
    __half* wT_h  = (__half*)wT;

    const long long DD = (long long)D_ * D_;

    WP wp;
    wp.w[0]  = Wq;       wp.w[1]  = Wk;       wp.w[2]  = Wv;
    wp.w[3]  = Wo;       wp.w[4]  = W1;       wp.w[5]  = W2;
    wp.w[6]  = Wq + DD;  wp.w[7]  = Wk + DD;  wp.w[8]  = Wv + DD;
    wp.w[9]  = Wo + DD;  wp.w[10] = W1 + DD;  wp.w[11] = W2 + DD;
    wp.w[12] = fc0w;

    // fork: wtrans on s1 concurrent with prep on main
    cudaEventRecord(ev[0], 0);
    cudaStreamWaitEvent(s1, ev[0], 0);
    wtrans_kernel<<<dim3(16, 16, NWMAT), dim3(32, 8), 0, s1>>>(wp, wT_h);
    cudaEventRecord(ev[1], s1);
    prep_kernel<<<dim3(D_ / 32, T_ / 32, B_), dim3(32, 8)>>>(x, pos, ewp, enc);
    cudaStreamWaitEvent(0, ev[1], 0);   // join before first use of wT

    const int MT = B_ * T_;   // 8192

    for (int l = 0; l < L_; l++) {
        int vo = l * D_;
        const __half* wq = wT_h + (l * 6 + 0) * DD;
        const __half* wk = wT_h + (l * 6 + 1) * DD;
        const __half* wv = wT_h + (l * 6 + 2) * DD;
        const __half* wo = wT_h + (l * 6 + 3) * DD;
        const __half* w1 = wT_h + (l * 6 + 4) * DD;
        const __half* w2 = wT_h + (l * 6 + 5) * DD;

        ln_kernel<<<MT / 8, dim3(32, 8)>>>(enc, tmp_h, ln1s + vo, ln1b + vo);

        // fork: V^T on s1 concurrent with QK GEMM + qk_softmax on main
        cudaEventRecord(ev[2 + 2 * l], 0);
        cudaStreamWaitEvent(s1, ev[2 + 2 * l], 0);
        TGArgs av;
        av.t[0] = {wv, tmp_h, v_h, bv + vo, nullptr, 2 | 4, MT, 7};
        tgemm_kernel<<<dim3(512, 1, 1), 128, TG_SMEM3, s1>>>(av);
        cudaEventRecord(ev[3 + 2 * l], s1);

        TGArgs aqk;
        aqk.t[0] = {tmp_h, wq, q_h, bq + vo, nullptr, 2, D_, 3};
        aqk.t[1] = {tmp_h, wk, k_h, bk + vo, nullptr, 2, D_, 3};
        tgemm_kernel<<<dim3(512, 1, 2), 128, TG_SMEM3>>>(aqk);

        qk_softmax_kernel<<<dim3(T_ / 64, 1, B_ * NH_), 256>>>(q_h, k_h, p_h);

        cudaStreamWaitEvent(0, ev[3 + 2 * l], 0);   // join: pv needs V^T
        pv_kernel<<<dim3(1, T_ / 128, B_ * NH_), 128, TG_SMEM3>>>(p_h, v_h, o_h);

        TGArgs ao; ao.t[0] = {o_h, wo, enc, bo + vo, enc, 0, D_, 3};
        tgemm_kernel<<<dim3(512, 1, 1), 128, TG_SMEM3>>>(ao);

        ln_kernel<<<MT / 8, dim3(32, 8)>>>(enc, tmp_h, ln2s + vo, ln2b + vo);
        TGArgs a1; a1.t[0] = {tmp_h, w1, o_h, b1 + vo, nullptr, 3, D_, 3};
        tgemm_kernel<<<dim3(512, 1, 1), 128, TG_SMEM3>>>(a1);
        TGArgs a2; a2.t[0] = {o_h, w2, enc, b2 + vo, enc, 0, D_, 3};
        tgemm_kernel<<<dim3(512, 1, 1), 128, TG_SMEM3>>>(a2);
    }

    ln_kernel<<<MT / 8, dim3(32, 8)>>>(enc, tmp_h, lnfs, lnfb);
    TGArgs af; af.t[0] = {tmp_h, wT_h + 12 * DD, q, fc0b, nullptr, 0, D_, 3};
    tgemm_kernel<<<dim3(512, 1, 1), 128, TG_SMEM3>>>(af);

    pvam_kernel<<<dim3(ML_ / 5, B_), 256>>>(q, emb, gwp, fc1, (float*)d_out);
}